// round 10
// baseline (speedup 1.0000x reference)
#include <cuda_runtime.h>
#include <cuda_bf16.h>
#include <stdint.h>

// ---------------------------------------------------------------------------
#define BATCH   2
#define SEQ     2048
#define DMODEL  1024
#define NHEADS  16
#define HDIM    64
#define MROWS   4096
#define QKV_N   3072

// ---------------------------------------------------------------------------
// Scratch (__device__ globals)
// ---------------------------------------------------------------------------
__device__ __nv_bfloat16 g_xh[(size_t)MROWS * DMODEL];
__device__ __nv_bfloat16 g_xl[(size_t)MROWS * DMODEL];
__device__ __nv_bfloat16 g_wqh[(size_t)QKV_N * DMODEL];
__device__ __nv_bfloat16 g_wql[(size_t)QKV_N * DMODEL];
__device__ __nv_bfloat16 g_woh[(size_t)DMODEL * DMODEL];
__device__ __nv_bfloat16 g_wol[(size_t)DMODEL * DMODEL];
__device__ __nv_bfloat16 g_qkvh[(size_t)MROWS * QKV_N];
__device__ __nv_bfloat16 g_qkvl[(size_t)MROWS * QKV_N];
__device__ __nv_bfloat16 g_ath[(size_t)MROWS * DMODEL];
__device__ __nv_bfloat16 g_atl[(size_t)MROWS * DMODEL];

// ---------------------------------------------------------------------------
// PTX helpers (all sm_80+ — safe on compute_103)
// ---------------------------------------------------------------------------
__device__ __forceinline__ uint32_t smem_u32(const void* p) {
    uint32_t a;
    asm("{ .reg .u64 t; cvta.to.shared.u64 t, %1; cvt.u32.u64 %0, t; }" : "=r"(a) : "l"(p));
    return a;
}
__device__ __forceinline__ void ldsm_x4(uint32_t* r, uint32_t addr) {
    asm volatile("ldmatrix.sync.aligned.m8n8.x4.shared.b16 {%0,%1,%2,%3}, [%4];"
                 : "=r"(r[0]), "=r"(r[1]), "=r"(r[2]), "=r"(r[3]) : "r"(addr));
}
__device__ __forceinline__ void ldsm_x4_t(uint32_t* r, uint32_t addr) {
    asm volatile("ldmatrix.sync.aligned.m8n8.x4.trans.shared.b16 {%0,%1,%2,%3}, [%4];"
                 : "=r"(r[0]), "=r"(r[1]), "=r"(r[2]), "=r"(r[3]) : "r"(addr));
}
__device__ __forceinline__ void mma16816(float* d, const uint32_t* a, const uint32_t* b) {
    asm volatile(
        "mma.sync.aligned.m16n8k16.row.col.f32.bf16.bf16.f32 "
        "{%0,%1,%2,%3}, {%4,%5,%6,%7}, {%8,%9}, {%0,%1,%2,%3};"
        : "+f"(d[0]), "+f"(d[1]), "+f"(d[2]), "+f"(d[3])
        : "r"(a[0]), "r"(a[1]), "r"(a[2]), "r"(a[3]), "r"(b[0]), "r"(b[1]));
}
__device__ __forceinline__ void cp16(uint32_t dst, const void* src) {
    asm volatile("cp.async.cg.shared.global [%0], [%1], 16;" :: "r"(dst), "l"(src));
}
#define CP_COMMIT() asm volatile("cp.async.commit_group;" ::: "memory")
#define CP_WAIT(n)  asm volatile("cp.async.wait_group %0;" :: "n"(n) : "memory")

__device__ __forceinline__ uint32_t pack_bf2(float a, float b) {
    __nv_bfloat162 t(__float2bfloat16(a), __float2bfloat16(b));
    return *(uint32_t*)&t;
}

// ---------------------------------------------------------------------------
// merged split: fp32 -> bf16 hi + lo for x, W_qkv, W_out in one launch
// ---------------------------------------------------------------------------
#define NX4 (MROWS * DMODEL / 4)
#define NQ4 (QKV_N * DMODEL / 4)
#define NO4 (DMODEL * DMODEL / 4)

__global__ __launch_bounds__(256) void split_all(
    const float* __restrict__ x, const float* __restrict__ wq, const float* __restrict__ wo,
    __nv_bfloat16* __restrict__ xh, __nv_bfloat16* __restrict__ xl,
    __nv_bfloat16* __restrict__ wqh, __nv_bfloat16* __restrict__ wql,
    __nv_bfloat16* __restrict__ woh, __nv_bfloat16* __restrict__ wol)
{
    int i = blockIdx.x * 256 + threadIdx.x;
    const float* src; __nv_bfloat16 *hi, *lo; int j;
    if (i < NX4)            { src = x;  hi = xh;  lo = xl;  j = i; }
    else if (i < NX4 + NQ4) { src = wq; hi = wqh; lo = wql; j = i - NX4; }
    else if (i < NX4 + NQ4 + NO4) { src = wo; hi = woh; lo = wol; j = i - NX4 - NQ4; }
    else return;

    float4 v = ((const float4*)src)[j];
    __nv_bfloat16 h0 = __float2bfloat16(v.x), h1 = __float2bfloat16(v.y);
    __nv_bfloat16 h2 = __float2bfloat16(v.z), h3 = __float2bfloat16(v.w);
    __nv_bfloat16 l0 = __float2bfloat16(v.x - __bfloat162float(h0));
    __nv_bfloat16 l1 = __float2bfloat16(v.y - __bfloat162float(h1));
    __nv_bfloat16 l2 = __float2bfloat16(v.z - __bfloat162float(h2));
    __nv_bfloat16 l3 = __float2bfloat16(v.w - __bfloat162float(h3));
    ((__nv_bfloat162*)hi)[2 * j]     = __nv_bfloat162(h0, h1);
    ((__nv_bfloat162*)hi)[2 * j + 1] = __nv_bfloat162(h2, h3);
    ((__nv_bfloat162*)lo)[2 * j]     = __nv_bfloat162(l0, l1);
    ((__nv_bfloat162*)lo)[2 * j + 1] = __nv_bfloat162(l2, l3);
}

// ---------------------------------------------------------------------------
// HMMA GEMM bf16x3-split, 3-stage cp.async pipeline, XOR-swizzled smem.
// C[M,N] = A[M,K] * B[N,K]^T ; SPLIT=1 writes bf16 hi/lo.
// ---------------------------------------------------------------------------
#define BM 128
#define BN 128
#define BK 32
#define GT_B  (BM * BK * 2)        // 8192 bytes / tile
#define GSTG_B (4 * GT_B)          // 32768 bytes / stage
#define GEMM_SMEM (3 * GSTG_B)     // 98304

__device__ __forceinline__ uint32_t gswz(int row, int c) {  // byte offset
    return (uint32_t)(row * BK + ((c ^ ((row >> 1) & 3)) << 3)) * 2;
}

template<int SPLIT>
__global__ __launch_bounds__(256, 2) void gemm_hmma(
    const __nv_bfloat16* __restrict__ Ah, const __nv_bfloat16* __restrict__ Al,
    const __nv_bfloat16* __restrict__ Bh, const __nv_bfloat16* __restrict__ Bl,
    float* __restrict__ C, __nv_bfloat16* __restrict__ Ch, __nv_bfloat16* __restrict__ Cl,
    int M, int N, int K)
{
    extern __shared__ __nv_bfloat16 dsm[];
    const uint32_t sb = smem_u32(dsm);
    const int tid = threadIdx.x;
    const int wid = tid >> 5;
    const int lid = tid & 31;
    const int warp_m = (wid & 3) * 32;
    const int warp_n = (wid >> 2) * 64;
    const int brow = blockIdx.y * BM;
    const int bcol = blockIdx.x * BN;

    float acc[2][8][4];
#pragma unroll
    for (int mf = 0; mf < 2; mf++)
#pragma unroll
        for (int nf = 0; nf < 8; nf++)
#pragma unroll
            for (int c = 0; c < 4; c++) acc[mf][nf][c] = 0.f;

    const int r0 = tid >> 2, c0 = tid & 3;
    const uint32_t o0 = gswz(r0, c0);
    const uint32_t o1 = gswz(r0 + 64, c0);
    const int nk = K / BK;

    auto issue = [&](int kt, int st) {
        size_t gA = (size_t)(brow + r0) * K + kt * BK + c0 * 8;
        size_t gB = (size_t)(bcol + r0) * K + kt * BK + c0 * 8;
        size_t gs = (size_t)64 * K;
        uint32_t d = sb + st * GSTG_B;
        cp16(d + o0,            Ah + gA);
        cp16(d + o1,            Ah + gA + gs);
        cp16(d + GT_B + o0,     Al + gA);
        cp16(d + GT_B + o1,     Al + gA + gs);
        cp16(d + 2 * GT_B + o0, Bh + gB);
        cp16(d + 2 * GT_B + o1, Bh + gB + gs);
        cp16(d + 3 * GT_B + o0, Bl + gB);
        cp16(d + 3 * GT_B + o1, Bl + gB + gs);
    };

    issue(0, 0); CP_COMMIT();
    issue(1, 1); CP_COMMIT();

    const int a_r = lid & 15;
    const int a_c = lid >> 4;
    const int b_r = (lid & 7) + ((lid >> 4) & 1) * 8;
    const int b_c = (lid >> 3) & 1;

    for (int kt = 0; kt < nk; kt++) {
        int st = kt - (kt / 3) * 3;
        CP_WAIT(1);
        __syncthreads();
        if (kt + 2 < nk) { int k2 = kt + 2; issue(k2, k2 - (k2 / 3) * 3); }
        CP_COMMIT();

        uint32_t uAh = sb + st * GSTG_B;
        uint32_t uAl = uAh + GT_B;
        uint32_t uBh = uAh + 2 * GT_B;
        uint32_t uBl = uAh + 3 * GT_B;

#pragma unroll
        for (int ks = 0; ks < 2; ks++) {
            uint32_t ah[2][4], al[2][4];
#pragma unroll
            for (int mf = 0; mf < 2; mf++) {
                uint32_t off = gswz(warp_m + mf * 16 + a_r, ks * 2 + a_c);
                ldsm_x4(ah[mf], uAh + off);
                ldsm_x4(al[mf], uAl + off);
            }
#pragma unroll
            for (int np = 0; np < 4; np++) {
                uint32_t bh[4], bl[4];
                uint32_t off = gswz(warp_n + np * 16 + b_r, ks * 2 + b_c);
                ldsm_x4(bh, uBh + off);
                ldsm_x4(bl, uBl + off);
#pragma unroll
                for (int f = 0; f < 2; f++) {
                    int nf = 2 * np + f;
#pragma unroll
                    for (int mf = 0; mf < 2; mf++) {
                        mma16816(acc[mf][nf], ah[mf], bh + 2 * f);
                        mma16816(acc[mf][nf], ah[mf], bl + 2 * f);
                        mma16816(acc[mf][nf], al[mf], bh + 2 * f);
                    }
                }
            }
        }
    }

    const int er = lid >> 2;
    const int ec = (lid & 3) * 2;
#pragma unroll
    for (int mf = 0; mf < 2; mf++) {
#pragma unroll
        for (int nf = 0; nf < 8; nf++) {
            int row = brow + warp_m + mf * 16 + er;
            int col = bcol + warp_n + nf * 8 + ec;
            if (SPLIT) {
#pragma unroll
                for (int half = 0; half < 2; half++) {
                    float v0 = acc[mf][nf][2 * half];
                    float v1 = acc[mf][nf][2 * half + 1];
                    __nv_bfloat16 h0 = __float2bfloat16(v0), h1 = __float2bfloat16(v1);
                    __nv_bfloat16 l0 = __float2bfloat16(v0 - __bfloat162float(h0));
                    __nv_bfloat16 l1 = __float2bfloat16(v1 - __bfloat162float(h1));
                    size_t o = (size_t)(row + 8 * half) * N + col;
                    *(__nv_bfloat162*)(Ch + o) = __nv_bfloat162(h0, h1);
                    *(__nv_bfloat162*)(Cl + o) = __nv_bfloat162(l0, l1);
                }
            } else {
                *(float2*)&C[(size_t)row * N + col] = make_float2(acc[mf][nf][0], acc[mf][nf][1]);
                *(float2*)&C[(size_t)(row + 8) * N + col] = make_float2(acc[mf][nf][2], acc[mf][nf][3]);
            }
        }
    }
}

// ---------------------------------------------------------------------------
// Flash attention (causal) on HMMA, Br = Bc = 64, 128 threads (4 warps),
// 2-stage cp.async pipeline (64KB/CTA -> 3 CTAs/SM), XOR swizzle.
// ---------------------------------------------------------------------------
#define FT_B   (64 * 64 * 2)        // 8192 bytes / tile
#define FSTG_B (4 * FT_B)           // 32768 bytes / stage (Kh,Kl,Vh,Vl)
#define FA_SMEM (2 * FSTG_B)        // 65536

__device__ __forceinline__ uint32_t fswz(int row, int c) {  // byte offset
    return (uint32_t)(row * 64 + ((c ^ (row & 7)) << 3)) * 2;
}

__global__ __launch_bounds__(128, 3) void flash_hmma(
    const __nv_bfloat16* __restrict__ qh_, const __nv_bfloat16* __restrict__ ql_,
    __nv_bfloat16* __restrict__ ath, __nv_bfloat16* __restrict__ atl)
{
    extern __shared__ __nv_bfloat16 fsm[];
    const uint32_t sb = smem_u32(fsm);
    const int tid = threadIdx.x;
    const int wid = tid >> 5;
    const int lane = tid & 31;
    const int qt = (int)gridDim.x - 1 - (int)blockIdx.x;   // heavy first
    const int bh = blockIdx.y;
    const int b = bh >> 4;
    const int h = bh & 15;
    const int rowbase = b * SEQ;
    const int q0 = qt * 64;
    const int warp_m = wid * 16;

    // ---- stage Q into stage 0 (hi, lo slots), read to regs ----
#pragma unroll
    for (int i = 0; i < 4; i++) {
        int v = tid + i * 128;
        int r = v >> 3, c = v & 7;
        size_t g = (size_t)(rowbase + q0 + r) * QKV_N + h * HDIM + c * 8;
        uint32_t o = fswz(r, c);
        cp16(sb + o, qh_ + g);
        cp16(sb + FT_B + o, ql_ + g);
    }
    CP_COMMIT(); CP_WAIT(0);
    __syncthreads();

    uint32_t Qh[4][4], Ql[4][4];
#pragma unroll
    for (int ks = 0; ks < 4; ks++) {
        uint32_t off = fswz(warp_m + (lane & 15), ks * 2 + (lane >> 4));
        ldsm_x4(Qh[ks], sb + off);
        ldsm_x4(Ql[ks], sb + FT_B + off);
    }
    __syncthreads();

    float oacc[8][4];
#pragma unroll
    for (int nd = 0; nd < 8; nd++)
#pragma unroll
        for (int c = 0; c < 4; c++) oacc[nd][c] = 0.f;
    float m0 = -1e30f, m1 = -1e30f, l0 = 0.f, l1 = 0.f;
    const float scale = 0.125f;

    auto issue_kv = [&](int jt, int st) {
#pragma unroll
        for (int i = 0; i < 4; i++) {
            int v = tid + i * 128;
            int r = v >> 3, c = v & 7;
            size_t g = (size_t)(rowbase + jt * 64 + r) * QKV_N + h * HDIM + c * 8;
            uint32_t d = sb + st * FSTG_B + fswz(r, c);
            cp16(d,            qh_ + g + DMODEL);       // Kh
            cp16(d + FT_B,     ql_ + g + DMODEL);       // Kl
            cp16(d + 2 * FT_B, qh_ + g + 2 * DMODEL);   // Vh
            cp16(d + 3 * FT_B, ql_ + g + 2 * DMODEL);   // Vl
        }
    };

    issue_kv(0, 0); CP_COMMIT();

    const int qrow0 = warp_m + (lane >> 2);
    const int qrow1 = qrow0 + 8;
    const int k_r = (lane & 7) + ((lane >> 4) & 1) * 8;
    const int k_c = (lane >> 3) & 1;
    const int v_r = (lane & 7) + ((lane >> 3) & 1) * 8;
    const int v_c = (lane >> 4) & 1;

    for (int jt = 0; jt <= qt; jt++) {
        int st = jt & 1;
        CP_WAIT(0);              // only group jt outstanding here
        __syncthreads();         // all warps done reading stage st^1 (iter jt-1)
        if (jt + 1 <= qt) { issue_kv(jt + 1, st ^ 1); CP_COMMIT(); }

        uint32_t uKh = sb + st * FSTG_B;
        uint32_t uKl = uKh + FT_B;
        uint32_t uVh = uKh + 2 * FT_B;
        uint32_t uVl = uKh + 3 * FT_B;

        // ---- S = Q K^T ----
        float sacc[8][4];
#pragma unroll
        for (int nf = 0; nf < 8; nf++)
#pragma unroll
            for (int c = 0; c < 4; c++) sacc[nf][c] = 0.f;

#pragma unroll
        for (int ks = 0; ks < 4; ks++) {
#pragma unroll
            for (int np = 0; np < 4; np++) {
                uint32_t kh[4], kl[4];
                uint32_t off = fswz(np * 16 + k_r, ks * 2 + k_c);
                ldsm_x4(kh, uKh + off);
                ldsm_x4(kl, uKl + off);
#pragma unroll
                for (int f = 0; f < 2; f++) {
                    int nf = 2 * np + f;
                    mma16816(sacc[nf], Qh[ks], kh + 2 * f);
                    mma16816(sacc[nf], Qh[ks], kl + 2 * f);
                    mma16816(sacc[nf], Ql[ks], kh + 2 * f);
                }
            }
        }

        // ---- scale + causal mask ----
        if (jt == qt) {
#pragma unroll
            for (int nf = 0; nf < 8; nf++) {
                int col = nf * 8 + (lane & 3) * 2;
                sacc[nf][0] = (col     <= qrow0) ? sacc[nf][0] * scale : -1e30f;
                sacc[nf][1] = (col + 1 <= qrow0) ? sacc[nf][1] * scale : -1e30f;
                sacc[nf][2] = (col     <= qrow1) ? sacc[nf][2] * scale : -1e30f;
                sacc[nf][3] = (col + 1 <= qrow1) ? sacc[nf][3] * scale : -1e30f;
            }
        } else {
#pragma unroll
            for (int nf = 0; nf < 8; nf++)
#pragma unroll
                for (int c = 0; c < 4; c++) sacc[nf][c] *= scale;
        }

        // ---- online softmax ----
        float mx0 = -1e30f, mx1 = -1e30f;
#pragma unroll
        for (int nf = 0; nf < 8; nf++) {
            mx0 = fmaxf(mx0, fmaxf(sacc[nf][0], sacc[nf][1]));
            mx1 = fmaxf(mx1, fmaxf(sacc[nf][2], sacc[nf][3]));
        }
        mx0 = fmaxf(mx0, __shfl_xor_sync(0xffffffffu, mx0, 1));
        mx0 = fmaxf(mx0, __shfl_xor_sync(0xffffffffu, mx0, 2));
        mx1 = fmaxf(mx1, __shfl_xor_sync(0xffffffffu, mx1, 1));
        mx1 = fmaxf(mx1, __shfl_xor_sync(0xffffffffu, mx1, 2));
        float mn0 = fmaxf(m0, mx0), mn1 = fmaxf(m1, mx1);
        float al0 = __expf(m0 - mn0), al1 = __expf(m1 - mn1);
        float s0 = 0.f, s1 = 0.f;
#pragma unroll
        for (int nf = 0; nf < 8; nf++) {
            sacc[nf][0] = __expf(sacc[nf][0] - mn0); s0 += sacc[nf][0];
            sacc[nf][1] = __expf(sacc[nf][1] - mn0); s0 += sacc[nf][1];
            sacc[nf][2] = __expf(sacc[nf][2] - mn1); s1 += sacc[nf][2];
            sacc[nf][3] = __expf(sacc[nf][3] - mn1); s1 += sacc[nf][3];
        }
        s0 += __shfl_xor_sync(0xffffffffu, s0, 1);
        s0 += __shfl_xor_sync(0xffffffffu, s0, 2);
        s1 += __shfl_xor_sync(0xffffffffu, s1, 1);
        s1 += __shfl_xor_sync(0xffffffffu, s1, 2);
        l0 = l0 * al0 + s0; m0 = mn0;
        l1 = l1 * al1 + s1; m1 = mn1;
#pragma unroll
        for (int nd = 0; nd < 8; nd++) {
            oacc[nd][0] *= al0; oacc[nd][1] *= al0;
            oacc[nd][2] *= al1; oacc[nd][3] *= al1;
        }

        // ---- O += P V ----
#pragma unroll
        for (int kb = 0; kb < 4; kb++) {
            uint32_t pah[4], pal[4];
            {
                float v00 = sacc[2 * kb][0],     v01 = sacc[2 * kb][1];
                float v02 = sacc[2 * kb][2],     v03 = sacc[2 * kb][3];
                float v10 = sacc[2 * kb + 1][0], v11 = sacc[2 * kb + 1][1];
                float v12 = sacc[2 * kb + 1][2], v13 = sacc[2 * kb + 1][3];
                pah[0] = pack_bf2(v00, v01); pah[1] = pack_bf2(v02, v03);
                pah[2] = pack_bf2(v10, v11); pah[3] = pack_bf2(v12, v13);
                pal[0] = pack_bf2(v00 - __bfloat162float(__float2bfloat16(v00)),
                                  v01 - __bfloat162float(__float2bfloat16(v01)));
                pal[1] = pack_bf2(v02 - __bfloat162float(__float2bfloat16(v02)),
                                  v03 - __bfloat162float(__float2bfloat16(v03)));
                pal[2] = pack_bf2(v10 - __bfloat162float(__float2bfloat16(v10)),
                                  v11 - __bfloat162float(__float2bfloat16(v11)));
                pal[3] = pack_bf2(v12 - __bfloat162float(__float2bfloat16(v12)),
                                  v13 - __bfloat162float(__float2bfloat16(v13)));
            }
#pragma unroll
            for (int ndp = 0; ndp < 4; ndp++) {
                uint32_t vh[4], vl[4];
                uint32_t off = fswz(kb * 16 + v_r, ndp * 2 + v_c);
                ldsm_x4_t(vh, uVh + off);
                ldsm_x4_t(vl, uVl + off);
#pragma unroll
                for (int f = 0; f < 2; f++) {
                    int nd = 2 * ndp + f;
                    mma16816(oacc[nd], pah, vh + 2 * f);
                    mma16816(oacc[nd], pah, vl + 2 * f);
                    mma16816(oacc[nd], pal, vh + 2 * f);
                }
            }
        }
    }

    // ---- epilogue ----
    float inv0 = 1.f / l0, inv1 = 1.f / l1;
    int grow0 = rowbase + q0 + qrow0;
#pragma unroll
    for (int nd = 0; nd < 8; nd++) {
        int col = h * HDIM + nd * 8 + (lane & 3) * 2;
#pragma unroll
        for (int half = 0; half < 2; half++) {
            float v0 = oacc[nd][2 * half]     * (half ? inv1 : inv0);
            float v1 = oacc[nd][2 * half + 1] * (half ? inv1 : inv0);
            __nv_bfloat16 h0 = __float2bfloat16(v0), h1 = __float2bfloat16(v1);
            __nv_bfloat16 l0b = __float2bfloat16(v0 - __bfloat162float(h0));
            __nv_bfloat16 l1b = __float2bfloat16(v1 - __bfloat162float(h1));
            size_t o = (size_t)(grow0 + 8 * half) * DMODEL + col;
            *(__nv_bfloat162*)(ath + o) = __nv_bfloat162(h0, h1);
            *(__nv_bfloat162*)(atl + o) = __nv_bfloat162(l0b, l1b);
        }
    }
}

// ---------------------------------------------------------------------------
// Launch
// ---------------------------------------------------------------------------
extern "C" void kernel_launch(void* const* d_in, const int* in_sizes, int n_in,
                              void* d_out, int out_size)
{
    (void)in_sizes; (void)n_in; (void)out_size;
    const float* x     = (const float*)d_in[0];
    const float* W_qkv = (const float*)d_in[1];
    const float* W_out = (const float*)d_in[2];
    float* out = (float*)d_out;

    __nv_bfloat16 *xh, *xl, *wqh, *wql, *woh, *wol, *qkvh, *qkvl, *ath, *atl;
    cudaGetSymbolAddress((void**)&xh, g_xh);
    cudaGetSymbolAddress((void**)&xl, g_xl);
    cudaGetSymbolAddress((void**)&wqh, g_wqh);
    cudaGetSymbolAddress((void**)&wql, g_wql);
    cudaGetSymbolAddress((void**)&woh, g_woh);
    cudaGetSymbolAddress((void**)&wol, g_wol);
    cudaGetSymbolAddress((void**)&qkvh, g_qkvh);
    cudaGetSymbolAddress((void**)&qkvl, g_qkvl);
    cudaGetSymbolAddress((void**)&ath, g_ath);
    cudaGetSymbolAddress((void**)&atl, g_atl);

    cudaFuncSetAttribute(gemm_hmma<0>, cudaFuncAttributeMaxDynamicSharedMemorySize, GEMM_SMEM);
    cudaFuncSetAttribute(gemm_hmma<1>, cudaFuncAttributeMaxDynamicSharedMemorySize, GEMM_SMEM);
    cudaFuncSetAttribute(flash_hmma, cudaFuncAttributeMaxDynamicSharedMemorySize, FA_SMEM);

    split_all<<<(NX4 + NQ4 + NO4 + 255) / 256, 256>>>(
        x, W_qkv, W_out, xh, xl, wqh, wql, woh, wol);

    gemm_hmma<1><<<dim3(QKV_N / BN, MROWS / BM), 256, GEMM_SMEM>>>(
        xh, xl, wqh, wql, nullptr, qkvh, qkvl, MROWS, QKV_N, DMODEL);

    flash_hmma<<<dim3(SEQ / 64, BATCH * NHEADS), 128, FA_SMEM>>>(qkvh, qkvl, ath, atl);

    gemm_hmma<0><<<dim3(DMODEL / BN, MROWS / BM), 256, GEMM_SMEM>>>(
        ath, atl, woh, wol, out, nullptr, nullptr, MROWS, DMODEL, DMODEL);
}

// round 11
// speedup vs baseline: 1.0248x; 1.0248x over previous
#include <cuda_runtime.h>
#include <cuda_bf16.h>
#include <stdint.h>

// ---------------------------------------------------------------------------
#define BATCH   2
#define SEQ     2048
#define DMODEL  1024
#define NHEADS  16
#define HDIM    64
#define MROWS   4096
#define QKV_N   3072

// ---------------------------------------------------------------------------
// Scratch (__device__ globals)
// ---------------------------------------------------------------------------
__device__ __nv_bfloat16 g_xh[(size_t)MROWS * DMODEL];
__device__ __nv_bfloat16 g_xl[(size_t)MROWS * DMODEL];
__device__ __nv_bfloat16 g_wqh[(size_t)QKV_N * DMODEL];
__device__ __nv_bfloat16 g_wql[(size_t)QKV_N * DMODEL];
__device__ __nv_bfloat16 g_woh[(size_t)DMODEL * DMODEL];
__device__ __nv_bfloat16 g_wol[(size_t)DMODEL * DMODEL];
__device__ __nv_bfloat16 g_qkvh[(size_t)MROWS * QKV_N];
__device__ __nv_bfloat16 g_qkvl[(size_t)MROWS * QKV_N];
__device__ __nv_bfloat16 g_ath[(size_t)MROWS * DMODEL];
__device__ __nv_bfloat16 g_atl[(size_t)MROWS * DMODEL];

// ---------------------------------------------------------------------------
// PTX helpers (all sm_80+ — safe on compute_103)
// ---------------------------------------------------------------------------
__device__ __forceinline__ uint32_t smem_u32(const void* p) {
    uint32_t a;
    asm("{ .reg .u64 t; cvta.to.shared.u64 t, %1; cvt.u32.u64 %0, t; }" : "=r"(a) : "l"(p));
    return a;
}
__device__ __forceinline__ void ldsm_x4(uint32_t* r, uint32_t addr) {
    asm volatile("ldmatrix.sync.aligned.m8n8.x4.shared.b16 {%0,%1,%2,%3}, [%4];"
                 : "=r"(r[0]), "=r"(r[1]), "=r"(r[2]), "=r"(r[3]) : "r"(addr));
}
__device__ __forceinline__ void ldsm_x4_t(uint32_t* r, uint32_t addr) {
    asm volatile("ldmatrix.sync.aligned.m8n8.x4.trans.shared.b16 {%0,%1,%2,%3}, [%4];"
                 : "=r"(r[0]), "=r"(r[1]), "=r"(r[2]), "=r"(r[3]) : "r"(addr));
}
__device__ __forceinline__ void mma16816(float* d, const uint32_t* a, const uint32_t* b) {
    asm volatile(
        "mma.sync.aligned.m16n8k16.row.col.f32.bf16.bf16.f32 "
        "{%0,%1,%2,%3}, {%4,%5,%6,%7}, {%8,%9}, {%0,%1,%2,%3};"
        : "+f"(d[0]), "+f"(d[1]), "+f"(d[2]), "+f"(d[3])
        : "r"(a[0]), "r"(a[1]), "r"(a[2]), "r"(a[3]), "r"(b[0]), "r"(b[1]));
}
__device__ __forceinline__ void cp16(uint32_t dst, const void* src) {
    asm volatile("cp.async.cg.shared.global [%0], [%1], 16;" :: "r"(dst), "l"(src));
}
#define CP_COMMIT() asm volatile("cp.async.commit_group;" ::: "memory")
#define CP_WAIT(n)  asm volatile("cp.async.wait_group %0;" :: "n"(n) : "memory")

__device__ __forceinline__ uint32_t pack_bf2(float a, float b) {
    __nv_bfloat162 t(__float2bfloat16(a), __float2bfloat16(b));
    return *(uint32_t*)&t;
}
// exact scale by power of two on packed bf16x2 (exponent shift, no rounding)
__device__ __forceinline__ uint32_t scale_bf2(uint32_t v, __nv_bfloat162 s) {
    __nv_bfloat162 t = __hmul2(*(__nv_bfloat162*)&v, s);
    return *(uint32_t*)&t;
}

// ---------------------------------------------------------------------------
// merged split: fp32 -> bf16 hi + lo for x, W_qkv, W_out in one launch
// ---------------------------------------------------------------------------
#define NX4 (MROWS * DMODEL / 4)
#define NQ4 (QKV_N * DMODEL / 4)
#define NO4 (DMODEL * DMODEL / 4)

__global__ __launch_bounds__(256) void split_all(
    const float* __restrict__ x, const float* __restrict__ wq, const float* __restrict__ wo,
    __nv_bfloat16* __restrict__ xh, __nv_bfloat16* __restrict__ xl,
    __nv_bfloat16* __restrict__ wqh, __nv_bfloat16* __restrict__ wql,
    __nv_bfloat16* __restrict__ woh, __nv_bfloat16* __restrict__ wol)
{
    int i = blockIdx.x * 256 + threadIdx.x;
    const float* src; __nv_bfloat16 *hi, *lo; int j;
    if (i < NX4)            { src = x;  hi = xh;  lo = xl;  j = i; }
    else if (i < NX4 + NQ4) { src = wq; hi = wqh; lo = wql; j = i - NX4; }
    else if (i < NX4 + NQ4 + NO4) { src = wo; hi = woh; lo = wol; j = i - NX4 - NQ4; }
    else return;

    float4 v = ((const float4*)src)[j];
    __nv_bfloat16 h0 = __float2bfloat16(v.x), h1 = __float2bfloat16(v.y);
    __nv_bfloat16 h2 = __float2bfloat16(v.z), h3 = __float2bfloat16(v.w);
    __nv_bfloat16 l0 = __float2bfloat16(v.x - __bfloat162float(h0));
    __nv_bfloat16 l1 = __float2bfloat16(v.y - __bfloat162float(h1));
    __nv_bfloat16 l2 = __float2bfloat16(v.z - __bfloat162float(h2));
    __nv_bfloat16 l3 = __float2bfloat16(v.w - __bfloat162float(h3));
    ((__nv_bfloat162*)hi)[2 * j]     = __nv_bfloat162(h0, h1);
    ((__nv_bfloat162*)hi)[2 * j + 1] = __nv_bfloat162(h2, h3);
    ((__nv_bfloat162*)lo)[2 * j]     = __nv_bfloat162(l0, l1);
    ((__nv_bfloat162*)lo)[2 * j + 1] = __nv_bfloat162(l2, l3);
}

// ---------------------------------------------------------------------------
// HMMA GEMM bf16x3-split, 3-stage cp.async pipeline, XOR-swizzled smem.
// C[M,N] = A[M,K] * B[N,K]^T ; SPLIT=1 writes bf16 hi/lo.
// ---------------------------------------------------------------------------
#define BM 128
#define BN 128
#define BK 32
#define GT_B  (BM * BK * 2)        // 8192 bytes / tile
#define GSTG_B (4 * GT_B)          // 32768 bytes / stage
#define GEMM_SMEM (3 * GSTG_B)     // 98304

__device__ __forceinline__ uint32_t gswz(int row, int c) {  // byte offset
    return (uint32_t)(row * BK + ((c ^ ((row >> 1) & 3)) << 3)) * 2;
}

template<int SPLIT>
__global__ __launch_bounds__(256, 2) void gemm_hmma(
    const __nv_bfloat16* __restrict__ Ah, const __nv_bfloat16* __restrict__ Al,
    const __nv_bfloat16* __restrict__ Bh, const __nv_bfloat16* __restrict__ Bl,
    float* __restrict__ C, __nv_bfloat16* __restrict__ Ch, __nv_bfloat16* __restrict__ Cl,
    int M, int N, int K)
{
    extern __shared__ __nv_bfloat16 dsm[];
    const uint32_t sb = smem_u32(dsm);
    const int tid = threadIdx.x;
    const int wid = tid >> 5;
    const int lid = tid & 31;
    const int warp_m = (wid & 3) * 32;
    const int warp_n = (wid >> 2) * 64;
    const int brow = blockIdx.y * BM;
    const int bcol = blockIdx.x * BN;

    float acc[2][8][4];
#pragma unroll
    for (int mf = 0; mf < 2; mf++)
#pragma unroll
        for (int nf = 0; nf < 8; nf++)
#pragma unroll
            for (int c = 0; c < 4; c++) acc[mf][nf][c] = 0.f;

    const int r0 = tid >> 2, c0 = tid & 3;
    const uint32_t o0 = gswz(r0, c0);
    const uint32_t o1 = gswz(r0 + 64, c0);
    const int nk = K / BK;

    auto issue = [&](int kt, int st) {
        size_t gA = (size_t)(brow + r0) * K + kt * BK + c0 * 8;
        size_t gB = (size_t)(bcol + r0) * K + kt * BK + c0 * 8;
        size_t gs = (size_t)64 * K;
        uint32_t d = sb + st * GSTG_B;
        cp16(d + o0,            Ah + gA);
        cp16(d + o1,            Ah + gA + gs);
        cp16(d + GT_B + o0,     Al + gA);
        cp16(d + GT_B + o1,     Al + gA + gs);
        cp16(d + 2 * GT_B + o0, Bh + gB);
        cp16(d + 2 * GT_B + o1, Bh + gB + gs);
        cp16(d + 3 * GT_B + o0, Bl + gB);
        cp16(d + 3 * GT_B + o1, Bl + gB + gs);
    };

    issue(0, 0); CP_COMMIT();
    issue(1, 1); CP_COMMIT();

    const int a_r = lid & 15;
    const int a_c = lid >> 4;
    const int b_r = (lid & 7) + ((lid >> 4) & 1) * 8;
    const int b_c = (lid >> 3) & 1;

    for (int kt = 0; kt < nk; kt++) {
        int st = kt - (kt / 3) * 3;
        CP_WAIT(1);
        __syncthreads();
        if (kt + 2 < nk) { int k2 = kt + 2; issue(k2, k2 - (k2 / 3) * 3); }
        CP_COMMIT();

        uint32_t uAh = sb + st * GSTG_B;
        uint32_t uAl = uAh + GT_B;
        uint32_t uBh = uAh + 2 * GT_B;
        uint32_t uBl = uAh + 3 * GT_B;

#pragma unroll
        for (int ks = 0; ks < 2; ks++) {
            uint32_t ah[2][4], al[2][4];
#pragma unroll
            for (int mf = 0; mf < 2; mf++) {
                uint32_t off = gswz(warp_m + mf * 16 + a_r, ks * 2 + a_c);
                ldsm_x4(ah[mf], uAh + off);
                ldsm_x4(al[mf], uAl + off);
            }
#pragma unroll
            for (int np = 0; np < 4; np++) {
                uint32_t bh[4], bl[4];
                uint32_t off = gswz(warp_n + np * 16 + b_r, ks * 2 + b_c);
                ldsm_x4(bh, uBh + off);
                ldsm_x4(bl, uBl + off);
#pragma unroll
                for (int f = 0; f < 2; f++) {
                    int nf = 2 * np + f;
#pragma unroll
                    for (int mf = 0; mf < 2; mf++) {
                        mma16816(acc[mf][nf], ah[mf], bh + 2 * f);
                        mma16816(acc[mf][nf], ah[mf], bl + 2 * f);
                        mma16816(acc[mf][nf], al[mf], bh + 2 * f);
                    }
                }
            }
        }
    }

    const int er = lid >> 2;
    const int ec = (lid & 3) * 2;
#pragma unroll
    for (int mf = 0; mf < 2; mf++) {
#pragma unroll
        for (int nf = 0; nf < 8; nf++) {
            int row = brow + warp_m + mf * 16 + er;
            int col = bcol + warp_n + nf * 8 + ec;
            if (SPLIT) {
#pragma unroll
                for (int half = 0; half < 2; half++) {
                    float v0 = acc[mf][nf][2 * half];
                    float v1 = acc[mf][nf][2 * half + 1];
                    __nv_bfloat16 h0 = __float2bfloat16(v0), h1 = __float2bfloat16(v1);
                    __nv_bfloat16 l0 = __float2bfloat16(v0 - __bfloat162float(h0));
                    __nv_bfloat16 l1 = __float2bfloat16(v1 - __bfloat162float(h1));
                    size_t o = (size_t)(row + 8 * half) * N + col;
                    *(__nv_bfloat162*)(Ch + o) = __nv_bfloat162(h0, h1);
                    *(__nv_bfloat162*)(Cl + o) = __nv_bfloat162(l0, l1);
                }
            } else {
                *(float2*)&C[(size_t)row * N + col] = make_float2(acc[mf][nf][0], acc[mf][nf][1]);
                *(float2*)&C[(size_t)(row + 8) * N + col] = make_float2(acc[mf][nf][2], acc[mf][nf][3]);
            }
        }
    }
}

// ---------------------------------------------------------------------------
// Flash attention (causal) on HMMA, Br = Bc = 64, 128 threads (4 warps),
// 3-stage cp.async pipeline, XOR swizzle. Scale folded into Q (exact 2^-3).
// ---------------------------------------------------------------------------
#define FT_B   (64 * 64 * 2)        // 8192 bytes / tile
#define FSTG_B (4 * FT_B)           // 32768 bytes / stage (Kh,Kl,Vh,Vl)
#define FA_SMEM (3 * FSTG_B)        // 98304

__device__ __forceinline__ uint32_t fswz(int row, int c) {  // byte offset
    return (uint32_t)(row * 64 + ((c ^ (row & 7)) << 3)) * 2;
}

__global__ __launch_bounds__(128, 2) void flash_hmma(
    const __nv_bfloat16* __restrict__ qh_, const __nv_bfloat16* __restrict__ ql_,
    __nv_bfloat16* __restrict__ ath, __nv_bfloat16* __restrict__ atl)
{
    extern __shared__ __nv_bfloat16 fsm[];
    const uint32_t sb = smem_u32(fsm);
    const int tid = threadIdx.x;
    const int wid = tid >> 5;
    const int lane = tid & 31;
    const int qt = (int)gridDim.x - 1 - (int)blockIdx.x;   // heavy first
    const int bh = blockIdx.y;
    const int b = bh >> 4;
    const int h = bh & 15;
    const int rowbase = b * SEQ;
    const int q0 = qt * 64;
    const int warp_m = wid * 16;

    // ---- stage Q into stage 0 (hi, lo slots), read to regs ----
#pragma unroll
    for (int i = 0; i < 4; i++) {
        int v = tid + i * 128;
        int r = v >> 3, c = v & 7;
        size_t g = (size_t)(rowbase + q0 + r) * QKV_N + h * HDIM + c * 8;
        uint32_t o = fswz(r, c);
        cp16(sb + o, qh_ + g);
        cp16(sb + FT_B + o, ql_ + g);
    }
    CP_COMMIT(); CP_WAIT(0);
    __syncthreads();

    // fold softmax scale (2^-3, exact) into Q fragments
    const __nv_bfloat162 sc2 = __nv_bfloat162(__float2bfloat16(0.125f),
                                              __float2bfloat16(0.125f));
    uint32_t Qh[4][4], Ql[4][4];
#pragma unroll
    for (int ks = 0; ks < 4; ks++) {
        uint32_t off = fswz(warp_m + (lane & 15), ks * 2 + (lane >> 4));
        ldsm_x4(Qh[ks], sb + off);
        ldsm_x4(Ql[ks], sb + FT_B + off);
#pragma unroll
        for (int i = 0; i < 4; i++) {
            Qh[ks][i] = scale_bf2(Qh[ks][i], sc2);
            Ql[ks][i] = scale_bf2(Ql[ks][i], sc2);
        }
    }
    __syncthreads();

    float oacc[8][4];
#pragma unroll
    for (int nd = 0; nd < 8; nd++)
#pragma unroll
        for (int c = 0; c < 4; c++) oacc[nd][c] = 0.f;
    float m0 = -1e30f, m1 = -1e30f, l0 = 0.f, l1 = 0.f;

    auto issue_kv = [&](int jt, int st) {
#pragma unroll
        for (int i = 0; i < 4; i++) {
            int v = tid + i * 128;
            int r = v >> 3, c = v & 7;
            size_t g = (size_t)(rowbase + jt * 64 + r) * QKV_N + h * HDIM + c * 8;
            uint32_t d = sb + st * FSTG_B + fswz(r, c);
            cp16(d,            qh_ + g + DMODEL);       // Kh
            cp16(d + FT_B,     ql_ + g + DMODEL);       // Kl
            cp16(d + 2 * FT_B, qh_ + g + 2 * DMODEL);   // Vh
            cp16(d + 3 * FT_B, ql_ + g + 2 * DMODEL);   // Vl
        }
    };

    issue_kv(0, 0); CP_COMMIT();
    if (qt >= 1) issue_kv(1, 1);
    CP_COMMIT();

    const int qrow0 = warp_m + (lane >> 2);
    const int qrow1 = qrow0 + 8;
    const int k_r = (lane & 7) + ((lane >> 4) & 1) * 8;
    const int k_c = (lane >> 3) & 1;
    const int v_r = (lane & 7) + ((lane >> 3) & 1) * 8;
    const int v_c = (lane >> 4) & 1;

    for (int jt = 0; jt <= qt; jt++) {
        int st = jt - (jt / 3) * 3;
        CP_WAIT(1);
        __syncthreads();
        if (jt + 2 <= qt) { int j2 = jt + 2; issue_kv(j2, j2 - (j2 / 3) * 3); }
        CP_COMMIT();

        uint32_t uKh = sb + st * FSTG_B;
        uint32_t uKl = uKh + FT_B;
        uint32_t uVh = uKh + 2 * FT_B;
        uint32_t uVl = uKh + 3 * FT_B;

        // ---- S = (Q*scale) K^T ----
        float sacc[8][4];
#pragma unroll
        for (int nf = 0; nf < 8; nf++)
#pragma unroll
            for (int c = 0; c < 4; c++) sacc[nf][c] = 0.f;

#pragma unroll
        for (int ks = 0; ks < 4; ks++) {
#pragma unroll
            for (int np = 0; np < 4; np++) {
                uint32_t kh[4], kl[4];
                uint32_t off = fswz(np * 16 + k_r, ks * 2 + k_c);
                ldsm_x4(kh, uKh + off);
                ldsm_x4(kl, uKl + off);
#pragma unroll
                for (int f = 0; f < 2; f++) {
                    int nf = 2 * np + f;
                    mma16816(sacc[nf], Qh[ks], kh + 2 * f);
                    mma16816(sacc[nf], Qh[ks], kl + 2 * f);
                    mma16816(sacc[nf], Ql[ks], kh + 2 * f);
                }
            }
        }

        // ---- causal mask (scale already folded into Q) ----
        if (jt == qt) {
#pragma unroll
            for (int nf = 0; nf < 8; nf++) {
                int col = nf * 8 + (lane & 3) * 2;
                sacc[nf][0] = (col     <= qrow0) ? sacc[nf][0] : -1e30f;
                sacc[nf][1] = (col + 1 <= qrow0) ? sacc[nf][1] : -1e30f;
                sacc[nf][2] = (col     <= qrow1) ? sacc[nf][2] : -1e30f;
                sacc[nf][3] = (col + 1 <= qrow1) ? sacc[nf][3] : -1e30f;
            }
        }

        // ---- online softmax ----
        float mx0 = -1e30f, mx1 = -1e30f;
#pragma unroll
        for (int nf = 0; nf < 8; nf++) {
            mx0 = fmaxf(mx0, fmaxf(sacc[nf][0], sacc[nf][1]));
            mx1 = fmaxf(mx1, fmaxf(sacc[nf][2], sacc[nf][3]));
        }
        mx0 = fmaxf(mx0, __shfl_xor_sync(0xffffffffu, mx0, 1));
        mx0 = fmaxf(mx0, __shfl_xor_sync(0xffffffffu, mx0, 2));
        mx1 = fmaxf(mx1, __shfl_xor_sync(0xffffffffu, mx1, 1));
        mx1 = fmaxf(mx1, __shfl_xor_sync(0xffffffffu, mx1, 2));
        float mn0 = fmaxf(m0, mx0), mn1 = fmaxf(m1, mx1);
        float al0 = __expf(m0 - mn0), al1 = __expf(m1 - mn1);
        float s0 = 0.f, s1 = 0.f;
#pragma unroll
        for (int nf = 0; nf < 8; nf++) {
            sacc[nf][0] = __expf(sacc[nf][0] - mn0); s0 += sacc[nf][0];
            sacc[nf][1] = __expf(sacc[nf][1] - mn0); s0 += sacc[nf][1];
            sacc[nf][2] = __expf(sacc[nf][2] - mn1); s1 += sacc[nf][2];
            sacc[nf][3] = __expf(sacc[nf][3] - mn1); s1 += sacc[nf][3];
        }
        s0 += __shfl_xor_sync(0xffffffffu, s0, 1);
        s0 += __shfl_xor_sync(0xffffffffu, s0, 2);
        s1 += __shfl_xor_sync(0xffffffffu, s1, 1);
        s1 += __shfl_xor_sync(0xffffffffu, s1, 2);
        l0 = l0 * al0 + s0; m0 = mn0;
        l1 = l1 * al1 + s1; m1 = mn1;
#pragma unroll
        for (int nd = 0; nd < 8; nd++) {
            oacc[nd][0] *= al0; oacc[nd][1] *= al0;
            oacc[nd][2] *= al1; oacc[nd][3] *= al1;
        }

        // ---- O += P V ----
#pragma unroll
        for (int kb = 0; kb < 4; kb++) {
            uint32_t pah[4], pal[4];
            {
                float v00 = sacc[2 * kb][0],     v01 = sacc[2 * kb][1];
                float v02 = sacc[2 * kb][2],     v03 = sacc[2 * kb][3];
                float v10 = sacc[2 * kb + 1][0], v11 = sacc[2 * kb + 1][1];
                float v12 = sacc[2 * kb + 1][2], v13 = sacc[2 * kb + 1][3];
                pah[0] = pack_bf2(v00, v01); pah[1] = pack_bf2(v02, v03);
                pah[2] = pack_bf2(v10, v11); pah[3] = pack_bf2(v12, v13);
                pal[0] = pack_bf2(v00 - __bfloat162float(__float2bfloat16(v00)),
                                  v01 - __bfloat162float(__float2bfloat16(v01)));
                pal[1] = pack_bf2(v02 - __bfloat162float(__float2bfloat16(v02)),
                                  v03 - __bfloat162float(__float2bfloat16(v03)));
                pal[2] = pack_bf2(v10 - __bfloat162float(__float2bfloat16(v10)),
                                  v11 - __bfloat162float(__float2bfloat16(v11)));
                pal[3] = pack_bf2(v12 - __bfloat162float(__float2bfloat16(v12)),
                                  v13 - __bfloat162float(__float2bfloat16(v13)));
            }
#pragma unroll
            for (int ndp = 0; ndp < 4; ndp++) {
                uint32_t vh[4], vl[4];
                uint32_t off = fswz(kb * 16 + v_r, ndp * 2 + v_c);
                ldsm_x4_t(vh, uVh + off);
                ldsm_x4_t(vl, uVl + off);
#pragma unroll
                for (int f = 0; f < 2; f++) {
                    int nd = 2 * ndp + f;
                    mma16816(oacc[nd], pah, vh + 2 * f);
                    mma16816(oacc[nd], pah, vl + 2 * f);
                    mma16816(oacc[nd], pal, vh + 2 * f);
                }
            }
        }
    }

    // ---- epilogue ----
    float inv0 = 1.f / l0, inv1 = 1.f / l1;
    int grow0 = rowbase + q0 + qrow0;
#pragma unroll
    for (int nd = 0; nd < 8; nd++) {
        int col = h * HDIM + nd * 8 + (lane & 3) * 2;
#pragma unroll
        for (int half = 0; half < 2; half++) {
            float v0 = oacc[nd][2 * half]     * (half ? inv1 : inv0);
            float v1 = oacc[nd][2 * half + 1] * (half ? inv1 : inv0);
            __nv_bfloat16 h0 = __float2bfloat16(v0), h1 = __float2bfloat16(v1);
            __nv_bfloat16 l0b = __float2bfloat16(v0 - __bfloat162float(h0));
            __nv_bfloat16 l1b = __float2bfloat16(v1 - __bfloat162float(h1));
            size_t o = (size_t)(grow0 + 8 * half) * DMODEL + col;
            *(__nv_bfloat162*)(ath + o) = __nv_bfloat162(h0, h1);
            *(__nv_bfloat162*)(atl + o) = __nv_bfloat162(l0b, l1b);
        }
    }
}

// ---------------------------------------------------------------------------
// Launch
// ---------------------------------------------------------------------------
extern "C" void kernel_launch(void* const* d_in, const int* in_sizes, int n_in,
                              void* d_out, int out_size)
{
    (void)in_sizes; (void)n_in; (void)out_size;
    const float* x     = (const float*)d_in[0];
    const float* W_qkv = (const float*)d_in[1];
    const float* W_out = (const float*)d_in[2];
    float* out = (float*)d_out;

    __nv_bfloat16 *xh, *xl, *wqh, *wql, *woh, *wol, *qkvh, *qkvl, *ath, *atl;
    cudaGetSymbolAddress((void**)&xh, g_xh);
    cudaGetSymbolAddress((void**)&xl, g_xl);
    cudaGetSymbolAddress((void**)&wqh, g_wqh);
    cudaGetSymbolAddress((void**)&wql, g_wql);
    cudaGetSymbolAddress((void**)&woh, g_woh);
    cudaGetSymbolAddress((void**)&wol, g_wol);
    cudaGetSymbolAddress((void**)&qkvh, g_qkvh);
    cudaGetSymbolAddress((void**)&qkvl, g_qkvl);
    cudaGetSymbolAddress((void**)&ath, g_ath);
    cudaGetSymbolAddress((void**)&atl, g_atl);

    cudaFuncSetAttribute(gemm_hmma<0>, cudaFuncAttributeMaxDynamicSharedMemorySize, GEMM_SMEM);
    cudaFuncSetAttribute(gemm_hmma<1>, cudaFuncAttributeMaxDynamicSharedMemorySize, GEMM_SMEM);
    cudaFuncSetAttribute(flash_hmma, cudaFuncAttributeMaxDynamicSharedMemorySize, FA_SMEM);

    split_all<<<(NX4 + NQ4 + NO4 + 255) / 256, 256>>>(
        x, W_qkv, W_out, xh, xl, wqh, wql, woh, wol);

    gemm_hmma<1><<<dim3(QKV_N / BN, MROWS / BM), 256, GEMM_SMEM>>>(
        xh, xl, wqh, wql, nullptr, qkvh, qkvl, MROWS, QKV_N, DMODEL);

    flash_hmma<<<dim3(SEQ / 64, BATCH * NHEADS), 128, FA_SMEM>>>(qkvh, qkvl, ath, atl);

    gemm_hmma<0><<<dim3(DMODEL / BN, MROWS / BM), 256, GEMM_SMEM>>>(
        ath, atl, woh, wol, out, nullptr, nullptr, MROWS, DMODEL, DMODEL);
}

// round 12
// speedup vs baseline: 1.4602x; 1.4248x over previous
#include <cuda_runtime.h>
#include <cuda_fp16.h>
#include <stdint.h>

// ---------------------------------------------------------------------------
#define BATCH   2
#define SEQ     2048
#define DMODEL  1024
#define NHEADS  16
#define HDIM    64
#define MROWS   4096
#define QKV_N   3072

// ---------------------------------------------------------------------------
// Scratch (__device__ globals) — fp16x2 scheme: activations hi/lo, weights hi
// ---------------------------------------------------------------------------
__device__ __half g_xh[(size_t)MROWS * DMODEL];
__device__ __half g_xl[(size_t)MROWS * DMODEL];
__device__ __half g_wq[(size_t)QKV_N * DMODEL];
__device__ __half g_wo[(size_t)DMODEL * DMODEL];
__device__ __half g_qkvh[(size_t)MROWS * QKV_N];
__device__ __half g_qkvl[(size_t)MROWS * QKV_N];
__device__ __half g_ath[(size_t)MROWS * DMODEL];
__device__ __half g_atl[(size_t)MROWS * DMODEL];

// ---------------------------------------------------------------------------
// PTX helpers (all sm_80+ — safe on compute_103)
// ---------------------------------------------------------------------------
__device__ __forceinline__ uint32_t smem_u32(const void* p) {
    uint32_t a;
    asm("{ .reg .u64 t; cvta.to.shared.u64 t, %1; cvt.u32.u64 %0, t; }" : "=r"(a) : "l"(p));
    return a;
}
__device__ __forceinline__ void ldsm_x4(uint32_t* r, uint32_t addr) {
    asm volatile("ldmatrix.sync.aligned.m8n8.x4.shared.b16 {%0,%1,%2,%3}, [%4];"
                 : "=r"(r[0]), "=r"(r[1]), "=r"(r[2]), "=r"(r[3]) : "r"(addr));
}
__device__ __forceinline__ void ldsm_x4_t(uint32_t* r, uint32_t addr) {
    asm volatile("ldmatrix.sync.aligned.m8n8.x4.trans.shared.b16 {%0,%1,%2,%3}, [%4];"
                 : "=r"(r[0]), "=r"(r[1]), "=r"(r[2]), "=r"(r[3]) : "r"(addr));
}
__device__ __forceinline__ void mma16816(float* d, const uint32_t* a, const uint32_t* b) {
    asm volatile(
        "mma.sync.aligned.m16n8k16.row.col.f32.f16.f16.f32 "
        "{%0,%1,%2,%3}, {%4,%5,%6,%7}, {%8,%9}, {%0,%1,%2,%3};"
        : "+f"(d[0]), "+f"(d[1]), "+f"(d[2]), "+f"(d[3])
        : "r"(a[0]), "r"(a[1]), "r"(a[2]), "r"(a[3]), "r"(b[0]), "r"(b[1]));
}
__device__ __forceinline__ void cp16(uint32_t dst, const void* src) {
    asm volatile("cp.async.cg.shared.global [%0], [%1], 16;" :: "r"(dst), "l"(src));
}
#define CP_COMMIT() asm volatile("cp.async.commit_group;" ::: "memory")
#define CP_WAIT(n)  asm volatile("cp.async.wait_group %0;" :: "n"(n) : "memory")

__device__ __forceinline__ uint32_t pack_h2(float a, float b) {
    __half2 t = __floats2half2_rn(a, b);
    return *(uint32_t*)&t;
}
__device__ __forceinline__ uint32_t scale_h2(uint32_t v, __half2 s) {
    __half2 t = __hmul2(*(__half2*)&v, s);
    return *(uint32_t*)&t;
}

// ---------------------------------------------------------------------------
// merged split: fp32 -> fp16 hi (+ lo when lo != null), three tensors
// ---------------------------------------------------------------------------
#define NX4 (MROWS * DMODEL / 4)
#define NQ4 (QKV_N * DMODEL / 4)
#define NO4 (DMODEL * DMODEL / 4)

__global__ __launch_bounds__(256) void split_all(
    const float* __restrict__ x, const float* __restrict__ wq, const float* __restrict__ wo,
    __half* __restrict__ xh, __half* __restrict__ xl,
    __half* __restrict__ wqh, __half* __restrict__ woh)
{
    int i = blockIdx.x * 256 + threadIdx.x;
    const float* src; __half *hi, *lo; int j;
    if (i < NX4)            { src = x;  hi = xh;  lo = xl;      j = i; }
    else if (i < NX4 + NQ4) { src = wq; hi = wqh; lo = nullptr; j = i - NX4; }
    else if (i < NX4 + NQ4 + NO4) { src = wo; hi = woh; lo = nullptr; j = i - NX4 - NQ4; }
    else return;

    float4 v = ((const float4*)src)[j];
    __half h0 = __float2half(v.x), h1 = __float2half(v.y);
    __half h2 = __float2half(v.z), h3 = __float2half(v.w);
    ((__half2*)hi)[2 * j]     = __half2(h0, h1);
    ((__half2*)hi)[2 * j + 1] = __half2(h2, h3);
    if (lo) {
        __half l0 = __float2half(v.x - __half2float(h0));
        __half l1 = __float2half(v.y - __half2float(h1));
        __half l2 = __float2half(v.z - __half2float(h2));
        __half l3 = __float2half(v.w - __half2float(h3));
        ((__half2*)lo)[2 * j]     = __half2(l0, l1);
        ((__half2*)lo)[2 * j + 1] = __half2(l2, l3);
    }
}

// ---------------------------------------------------------------------------
// HMMA GEMM fp16x2: C[M,N] = (Ah+Al)[M,K] * B[N,K]^T, B single fp16.
// 3-stage cp.async pipeline, XOR-swizzled smem. SPLIT=1 writes fp16 hi/lo.
// ---------------------------------------------------------------------------
#define BM 128
#define BN 128
#define BK 32
#define GT_B  (BM * BK * 2)        // 8192 bytes / tile
#define GSTG_B (3 * GT_B)          // 24576 bytes / stage (Ah, Al, B)
#define GEMM_SMEM (3 * GSTG_B)     // 73728

__device__ __forceinline__ uint32_t gswz(int row, int c) {  // byte offset
    return (uint32_t)(row * BK + ((c ^ ((row >> 1) & 3)) << 3)) * 2;
}

template<int SPLIT>
__global__ __launch_bounds__(256, 2) void gemm_hmma(
    const __half* __restrict__ Ah, const __half* __restrict__ Al,
    const __half* __restrict__ B,
    float* __restrict__ C, __half* __restrict__ Ch, __half* __restrict__ Cl,
    int M, int N, int K)
{
    extern __shared__ __half dsm[];
    const uint32_t sb = smem_u32(dsm);
    const int tid = threadIdx.x;
    const int wid = tid >> 5;
    const int lid = tid & 31;
    const int warp_m = (wid & 3) * 32;
    const int warp_n = (wid >> 2) * 64;
    const int brow = blockIdx.y * BM;
    const int bcol = blockIdx.x * BN;

    float acc[2][8][4];
#pragma unroll
    for (int mf = 0; mf < 2; mf++)
#pragma unroll
        for (int nf = 0; nf < 8; nf++)
#pragma unroll
            for (int c = 0; c < 4; c++) acc[mf][nf][c] = 0.f;

    const int r0 = tid >> 2, c0 = tid & 3;
    const uint32_t o0 = gswz(r0, c0);
    const uint32_t o1 = gswz(r0 + 64, c0);
    const int nk = K / BK;

    auto issue = [&](int kt, int st) {
        size_t gA = (size_t)(brow + r0) * K + kt * BK + c0 * 8;
        size_t gB = (size_t)(bcol + r0) * K + kt * BK + c0 * 8;
        size_t gs = (size_t)64 * K;
        uint32_t d = sb + st * GSTG_B;
        cp16(d + o0,            Ah + gA);
        cp16(d + o1,            Ah + gA + gs);
        cp16(d + GT_B + o0,     Al + gA);
        cp16(d + GT_B + o1,     Al + gA + gs);
        cp16(d + 2 * GT_B + o0, B + gB);
        cp16(d + 2 * GT_B + o1, B + gB + gs);
    };

    issue(0, 0); CP_COMMIT();
    issue(1, 1); CP_COMMIT();

    const int a_r = lid & 15;
    const int a_c = lid >> 4;
    const int b_r = (lid & 7) + ((lid >> 4) & 1) * 8;
    const int b_c = (lid >> 3) & 1;

    for (int kt = 0; kt < nk; kt++) {
        int st = kt - (kt / 3) * 3;
        CP_WAIT(1);
        __syncthreads();
        if (kt + 2 < nk) { int k2 = kt + 2; issue(k2, k2 - (k2 / 3) * 3); }
        CP_COMMIT();

        uint32_t uAh = sb + st * GSTG_B;
        uint32_t uAl = uAh + GT_B;
        uint32_t uB  = uAh + 2 * GT_B;

#pragma unroll
        for (int ks = 0; ks < 2; ks++) {
            uint32_t ah[2][4], al[2][4];
#pragma unroll
            for (int mf = 0; mf < 2; mf++) {
                uint32_t off = gswz(warp_m + mf * 16 + a_r, ks * 2 + a_c);
                ldsm_x4(ah[mf], uAh + off);
                ldsm_x4(al[mf], uAl + off);
            }
#pragma unroll
            for (int np = 0; np < 4; np++) {
                uint32_t bb[4];
                uint32_t off = gswz(warp_n + np * 16 + b_r, ks * 2 + b_c);
                ldsm_x4(bb, uB + off);
#pragma unroll
                for (int f = 0; f < 2; f++) {
                    int nf = 2 * np + f;
#pragma unroll
                    for (int mf = 0; mf < 2; mf++) {
                        mma16816(acc[mf][nf], ah[mf], bb + 2 * f);
                        mma16816(acc[mf][nf], al[mf], bb + 2 * f);
                    }
                }
            }
        }
    }

    const int er = lid >> 2;
    const int ec = (lid & 3) * 2;
#pragma unroll
    for (int mf = 0; mf < 2; mf++) {
#pragma unroll
        for (int nf = 0; nf < 8; nf++) {
            int row = brow + warp_m + mf * 16 + er;
            int col = bcol + warp_n + nf * 8 + ec;
            if (SPLIT) {
#pragma unroll
                for (int half = 0; half < 2; half++) {
                    float v0 = acc[mf][nf][2 * half];
                    float v1 = acc[mf][nf][2 * half + 1];
                    __half h0 = __float2half(v0), h1 = __float2half(v1);
                    __half l0 = __float2half(v0 - __half2float(h0));
                    __half l1 = __float2half(v1 - __half2float(h1));
                    size_t o = (size_t)(row + 8 * half) * N + col;
                    *(__half2*)(Ch + o) = __half2(h0, h1);
                    *(__half2*)(Cl + o) = __half2(l0, l1);
                }
            } else {
                *(float2*)&C[(size_t)row * N + col] = make_float2(acc[mf][nf][0], acc[mf][nf][1]);
                *(float2*)&C[(size_t)(row + 8) * N + col] = make_float2(acc[mf][nf][2], acc[mf][nf][3]);
            }
        }
    }
}

// ---------------------------------------------------------------------------
// Flash attention (causal) on HMMA fp16x2: Q split hi/lo, K,V single fp16.
// Br = Bc = 64, 128 threads (4 warps), 3-stage cp.async pipeline, XOR swizzle.
// Scale folded into Q (exact 2^-3).
// ---------------------------------------------------------------------------
#define FT_B   (64 * 64 * 2)        // 8192 bytes / tile
#define FSTG_B (2 * FT_B)           // 16384 bytes / stage (K, V)
#define FA_SMEM (3 * FSTG_B)        // 49152

__device__ __forceinline__ uint32_t fswz(int row, int c) {  // byte offset
    return (uint32_t)(row * 64 + ((c ^ (row & 7)) << 3)) * 2;
}

__global__ __launch_bounds__(128, 2) void flash_hmma(
    const __half* __restrict__ qh_, const __half* __restrict__ ql_,
    __half* __restrict__ ath, __half* __restrict__ atl)
{
    extern __shared__ __half fsm[];
    const uint32_t sb = smem_u32(fsm);
    const int tid = threadIdx.x;
    const int wid = tid >> 5;
    const int lane = tid & 31;
    const int qt = (int)gridDim.x - 1 - (int)blockIdx.x;   // heavy first
    const int bh = blockIdx.y;
    const int b = bh >> 4;
    const int h = bh & 15;
    const int rowbase = b * SEQ;
    const int q0 = qt * 64;
    const int warp_m = wid * 16;

    // ---- stage Q (hi at sb, lo at sb+FT_B), read to regs ----
#pragma unroll
    for (int i = 0; i < 4; i++) {
        int v = tid + i * 128;
        int r = v >> 3, c = v & 7;
        size_t g = (size_t)(rowbase + q0 + r) * QKV_N + h * HDIM + c * 8;
        uint32_t o = fswz(r, c);
        cp16(sb + o, qh_ + g);
        cp16(sb + FT_B + o, ql_ + g);
    }
    CP_COMMIT(); CP_WAIT(0);
    __syncthreads();

    // fold softmax scale (2^-3, exact) into Q fragments
    const __half2 sc2 = __half2(__float2half(0.125f), __float2half(0.125f));
    uint32_t Qh[4][4], Ql[4][4];
#pragma unroll
    for (int ks = 0; ks < 4; ks++) {
        uint32_t off = fswz(warp_m + (lane & 15), ks * 2 + (lane >> 4));
        ldsm_x4(Qh[ks], sb + off);
        ldsm_x4(Ql[ks], sb + FT_B + off);
#pragma unroll
        for (int i = 0; i < 4; i++) {
            Qh[ks][i] = scale_h2(Qh[ks][i], sc2);
            Ql[ks][i] = scale_h2(Ql[ks][i], sc2);
        }
    }
    __syncthreads();

    float oacc[8][4];
#pragma unroll
    for (int nd = 0; nd < 8; nd++)
#pragma unroll
        for (int c = 0; c < 4; c++) oacc[nd][c] = 0.f;
    float m0 = -1e30f, m1 = -1e30f, l0 = 0.f, l1 = 0.f;

    auto issue_kv = [&](int jt, int st) {
#pragma unroll
        for (int i = 0; i < 4; i++) {
            int v = tid + i * 128;
            int r = v >> 3, c = v & 7;
            size_t g = (size_t)(rowbase + jt * 64 + r) * QKV_N + h * HDIM + c * 8;
            uint32_t d = sb + st * FSTG_B + fswz(r, c);
            cp16(d,        qh_ + g + DMODEL);       // K (single fp16)
            cp16(d + FT_B, qh_ + g + 2 * DMODEL);   // V (single fp16)
        }
    };

    issue_kv(0, 0); CP_COMMIT();
    if (qt >= 1) issue_kv(1, 1);
    CP_COMMIT();

    const int qrow0 = warp_m + (lane >> 2);
    const int qrow1 = qrow0 + 8;
    const int k_r = (lane & 7) + ((lane >> 4) & 1) * 8;
    const int k_c = (lane >> 3) & 1;
    const int v_r = (lane & 7) + ((lane >> 3) & 1) * 8;
    const int v_c = (lane >> 4) & 1;

    for (int jt = 0; jt <= qt; jt++) {
        int st = jt - (jt / 3) * 3;
        CP_WAIT(1);
        __syncthreads();
        if (jt + 2 <= qt) { int j2 = jt + 2; issue_kv(j2, j2 - (j2 / 3) * 3); }
        CP_COMMIT();

        uint32_t uK = sb + st * FSTG_B;
        uint32_t uV = uK + FT_B;

        // ---- S = (Q*scale) K^T  (Qh + Ql passes, K single) ----
        float sacc[8][4];
#pragma unroll
        for (int nf = 0; nf < 8; nf++)
#pragma unroll
            for (int c = 0; c < 4; c++) sacc[nf][c] = 0.f;

#pragma unroll
        for (int ks = 0; ks < 4; ks++) {
#pragma unroll
            for (int np = 0; np < 4; np++) {
                uint32_t kk[4];
                uint32_t off = fswz(np * 16 + k_r, ks * 2 + k_c);
                ldsm_x4(kk, uK + off);
#pragma unroll
                for (int f = 0; f < 2; f++) {
                    int nf = 2 * np + f;
                    mma16816(sacc[nf], Qh[ks], kk + 2 * f);
                    mma16816(sacc[nf], Ql[ks], kk + 2 * f);
                }
            }
        }

        // ---- causal mask (scale already folded into Q) ----
        if (jt == qt) {
#pragma unroll
            for (int nf = 0; nf < 8; nf++) {
                int col = nf * 8 + (lane & 3) * 2;
                sacc[nf][0] = (col     <= qrow0) ? sacc[nf][0] : -1e30f;
                sacc[nf][1] = (col + 1 <= qrow0) ? sacc[nf][1] : -1e30f;
                sacc[nf][2] = (col     <= qrow1) ? sacc[nf][2] : -1e30f;
                sacc[nf][3] = (col + 1 <= qrow1) ? sacc[nf][3] : -1e30f;
            }
        }

        // ---- online softmax ----
        float mx0 = -1e30f, mx1 = -1e30f;
#pragma unroll
        for (int nf = 0; nf < 8; nf++) {
            mx0 = fmaxf(mx0, fmaxf(sacc[nf][0], sacc[nf][1]));
            mx1 = fmaxf(mx1, fmaxf(sacc[nf][2], sacc[nf][3]));
        }
        mx0 = fmaxf(mx0, __shfl_xor_sync(0xffffffffu, mx0, 1));
        mx0 = fmaxf(mx0, __shfl_xor_sync(0xffffffffu, mx0, 2));
        mx1 = fmaxf(mx1, __shfl_xor_sync(0xffffffffu, mx1, 1));
        mx1 = fmaxf(mx1, __shfl_xor_sync(0xffffffffu, mx1, 2));
        float mn0 = fmaxf(m0, mx0), mn1 = fmaxf(m1, mx1);
        float al0 = __expf(m0 - mn0), al1 = __expf(m1 - mn1);
        float s0 = 0.f, s1 = 0.f;
#pragma unroll
        for (int nf = 0; nf < 8; nf++) {
            sacc[nf][0] = __expf(sacc[nf][0] - mn0); s0 += sacc[nf][0];
            sacc[nf][1] = __expf(sacc[nf][1] - mn0); s0 += sacc[nf][1];
            sacc[nf][2] = __expf(sacc[nf][2] - mn1); s1 += sacc[nf][2];
            sacc[nf][3] = __expf(sacc[nf][3] - mn1); s1 += sacc[nf][3];
        }
        s0 += __shfl_xor_sync(0xffffffffu, s0, 1);
        s0 += __shfl_xor_sync(0xffffffffu, s0, 2);
        s1 += __shfl_xor_sync(0xffffffffu, s1, 1);
        s1 += __shfl_xor_sync(0xffffffffu, s1, 2);
        l0 = l0 * al0 + s0; m0 = mn0;
        l1 = l1 * al1 + s1; m1 = mn1;
#pragma unroll
        for (int nd = 0; nd < 8; nd++) {
            oacc[nd][0] *= al0; oacc[nd][1] *= al0;
            oacc[nd][2] *= al1; oacc[nd][3] *= al1;
        }

        // ---- O += P V  (P split fp16 hi/lo, V single) ----
#pragma unroll
        for (int kb = 0; kb < 4; kb++) {
            uint32_t pah[4], pal[4];
            {
                float v00 = sacc[2 * kb][0],     v01 = sacc[2 * kb][1];
                float v02 = sacc[2 * kb][2],     v03 = sacc[2 * kb][3];
                float v10 = sacc[2 * kb + 1][0], v11 = sacc[2 * kb + 1][1];
                float v12 = sacc[2 * kb + 1][2], v13 = sacc[2 * kb + 1][3];
                pah[0] = pack_h2(v00, v01); pah[1] = pack_h2(v02, v03);
                pah[2] = pack_h2(v10, v11); pah[3] = pack_h2(v12, v13);
                pal[0] = pack_h2(v00 - __half2float(__float2half(v00)),
                                 v01 - __half2float(__float2half(v01)));
                pal[1] = pack_h2(v02 - __half2float(__float2half(v02)),
                                 v03 - __half2float(__float2half(v03)));
                pal[2] = pack_h2(v10 - __half2float(__float2half(v10)),
                                 v11 - __half2float(__float2half(v11)));
                pal[3] = pack_h2(v12 - __half2float(__float2half(v12)),
                                 v13 - __half2float(__float2half(v13)));
            }
#pragma unroll
            for (int ndp = 0; ndp < 4; ndp++) {
                uint32_t vv[4];
                uint32_t off = fswz(kb * 16 + v_r, ndp * 2 + v_c);
                ldsm_x4_t(vv, uV + off);
#pragma unroll
                for (int f = 0; f < 2; f++) {
                    int nd = 2 * ndp + f;
                    mma16816(oacc[nd], pah, vv + 2 * f);
                    mma16816(oacc[nd], pal, vv + 2 * f);
                }
            }
        }
    }

    // ---- epilogue: normalize, split fp16 hi/lo ----
    float inv0 = 1.f / l0, inv1 = 1.f / l1;
    int grow0 = rowbase + q0 + qrow0;
#pragma unroll
    for (int nd = 0; nd < 8; nd++) {
        int col = h * HDIM + nd * 8 + (lane & 3) * 2;
#pragma unroll
        for (int half = 0; half < 2; half++) {
            float v0 = oacc[nd][2 * half]     * (half ? inv1 : inv0);
            float v1 = oacc[nd][2 * half + 1] * (half ? inv1 : inv0);
            __half h0 = __float2half(v0), h1 = __float2half(v1);
            __half l0b = __float2half(v0 - __half2float(h0));
            __half l1b = __float2half(v1 - __half2float(h1));
            size_t o = (size_t)(grow0 + 8 * half) * DMODEL + col;
            *(__half2*)(ath + o) = __half2(h0, h1);
            *(__half2*)(atl + o) = __half2(l0b, l1b);
        }
    }
}

// ---------------------------------------------------------------------------
// Launch
// ---------------------------------------------------------------------------
extern "C" void kernel_launch(void* const* d_in, const int* in_sizes, int n_in,
                              void* d_out, int out_size)
{
    (void)in_sizes; (void)n_in; (void)out_size;
    const float* x     = (const float*)d_in[0];
    const float* W_qkv = (const float*)d_in[1];
    const float* W_out = (const float*)d_in[2];
    float* out = (float*)d_out;

    __half *xh, *xl, *wq, *wo, *qkvh, *qkvl, *ath, *atl;
    cudaGetSymbolAddress((void**)&xh, g_xh);
    cudaGetSymbolAddress((void**)&xl, g_xl);
    cudaGetSymbolAddress((void**)&wq, g_wq);
    cudaGetSymbolAddress((void**)&wo, g_wo);
    cudaGetSymbolAddress((void**)&qkvh, g_qkvh);
    cudaGetSymbolAddress((void**)&qkvl, g_qkvl);
    cudaGetSymbolAddress((void**)&ath, g_ath);
    cudaGetSymbolAddress((void**)&atl, g_atl);

    cudaFuncSetAttribute(gemm_hmma<0>, cudaFuncAttributeMaxDynamicSharedMemorySize, GEMM_SMEM);
    cudaFuncSetAttribute(gemm_hmma<1>, cudaFuncAttributeMaxDynamicSharedMemorySize, GEMM_SMEM);
    cudaFuncSetAttribute(flash_hmma, cudaFuncAttributeMaxDynamicSharedMemorySize, FA_SMEM);

    split_all<<<(NX4 + NQ4 + NO4 + 255) / 256, 256>>>(
        x, W_qkv, W_out, xh, xl, wq, wo);

    // 1) QKV projection -> fp16 hi/lo
    gemm_hmma<1><<<dim3(QKV_N / BN, MROWS / BM), 256, GEMM_SMEM>>>(
        xh, xl, wq, nullptr, qkvh, qkvl, MROWS, QKV_N, DMODEL);

    // 2) causal flash attention -> fp16 hi/lo
    flash_hmma<<<dim3(SEQ / 64, BATCH * NHEADS), 128, FA_SMEM>>>(qkvh, qkvl, ath, atl);

    // 3) output projection -> fp32
    gemm_hmma<0><<<dim3(DMODEL / BN, MROWS / BM), 256, GEMM_SMEM>>>(
        ath, atl, wo, out, nullptr, nullptr, MROWS, DMODEL, DMODEL);
}

// round 13
// speedup vs baseline: 1.5924x; 1.0906x over previous
#include <cuda_runtime.h>
#include <cuda_fp16.h>
#include <stdint.h>

// ---------------------------------------------------------------------------
#define BATCH   2
#define SEQ     2048
#define DMODEL  1024
#define NHEADS  16
#define HDIM    64
#define MROWS   4096
#define QKV_N   3072

// ---------------------------------------------------------------------------
// Scratch (__device__ globals)
// ---------------------------------------------------------------------------
__device__ __half g_xh[(size_t)MROWS * DMODEL];
__device__ __half g_xl[(size_t)MROWS * DMODEL];
__device__ __half g_wq[(size_t)QKV_N * DMODEL];
__device__ __half g_wo[(size_t)DMODEL * DMODEL];
__device__ __half g_qkv[(size_t)MROWS * QKV_N];       // single fp16
__device__ __half g_ath[(size_t)MROWS * DMODEL];
__device__ __half g_atl[(size_t)MROWS * DMODEL];

// ---------------------------------------------------------------------------
// PTX helpers (all sm_80+ — safe on compute_103)
// ---------------------------------------------------------------------------
__device__ __forceinline__ uint32_t smem_u32(const void* p) {
    uint32_t a;
    asm("{ .reg .u64 t; cvta.to.shared.u64 t, %1; cvt.u32.u64 %0, t; }" : "=r"(a) : "l"(p));
    return a;
}
__device__ __forceinline__ void ldsm_x4(uint32_t* r, uint32_t addr) {
    asm volatile("ldmatrix.sync.aligned.m8n8.x4.shared.b16 {%0,%1,%2,%3}, [%4];"
                 : "=r"(r[0]), "=r"(r[1]), "=r"(r[2]), "=r"(r[3]) : "r"(addr));
}
__device__ __forceinline__ void ldsm_x4_t(uint32_t* r, uint32_t addr) {
    asm volatile("ldmatrix.sync.aligned.m8n8.x4.trans.shared.b16 {%0,%1,%2,%3}, [%4];"
                 : "=r"(r[0]), "=r"(r[1]), "=r"(r[2]), "=r"(r[3]) : "r"(addr));
}
__device__ __forceinline__ void mma16816(float* d, const uint32_t* a, const uint32_t* b) {
    asm volatile(
        "mma.sync.aligned.m16n8k16.row.col.f32.f16.f16.f32 "
        "{%0,%1,%2,%3}, {%4,%5,%6,%7}, {%8,%9}, {%0,%1,%2,%3};"
        : "+f"(d[0]), "+f"(d[1]), "+f"(d[2]), "+f"(d[3])
        : "r"(a[0]), "r"(a[1]), "r"(a[2]), "r"(a[3]), "r"(b[0]), "r"(b[1]));
}
__device__ __forceinline__ void cp16(uint32_t dst, const void* src) {
    asm volatile("cp.async.cg.shared.global [%0], [%1], 16;" :: "r"(dst), "l"(src));
}
#define CP_COMMIT() asm volatile("cp.async.commit_group;" ::: "memory")
#define CP_WAIT(n)  asm volatile("cp.async.wait_group %0;" :: "n"(n) : "memory")

__device__ __forceinline__ uint32_t pack_h2(float a, float b) {
    __half2 t = __floats2half2_rn(a, b);
    return *(uint32_t*)&t;
}
__device__ __forceinline__ uint32_t scale_h2(uint32_t v, __half2 s) {
    __half2 t = __hmul2(*(__half2*)&v, s);
    return *(uint32_t*)&t;
}

// ---------------------------------------------------------------------------
// merged split: fp32 -> fp16 hi (+ lo for x only), three tensors
// ---------------------------------------------------------------------------
#define NX4 (MROWS * DMODEL / 4)
#define NQ4 (QKV_N * DMODEL / 4)
#define NO4 (DMODEL * DMODEL / 4)

__global__ __launch_bounds__(256) void split_all(
    const float* __restrict__ x, const float* __restrict__ wq, const float* __restrict__ wo,
    __half* __restrict__ xh, __half* __restrict__ xl,
    __half* __restrict__ wqh, __half* __restrict__ woh)
{
    int i = blockIdx.x * 256 + threadIdx.x;
    const float* src; __half *hi, *lo; int j;
    if (i < NX4)            { src = x;  hi = xh;  lo = xl;      j = i; }
    else if (i < NX4 + NQ4) { src = wq; hi = wqh; lo = nullptr; j = i - NX4; }
    else if (i < NX4 + NQ4 + NO4) { src = wo; hi = woh; lo = nullptr; j = i - NX4 - NQ4; }
    else return;

    float4 v = ((const float4*)src)[j];
    __half h0 = __float2half(v.x), h1 = __float2half(v.y);
    __half h2 = __float2half(v.z), h3 = __float2half(v.w);
    ((__half2*)hi)[2 * j]     = __half2(h0, h1);
    ((__half2*)hi)[2 * j + 1] = __half2(h2, h3);
    if (lo) {
        __half l0 = __float2half(v.x - __half2float(h0));
        __half l1 = __float2half(v.y - __half2float(h1));
        __half l2 = __float2half(v.z - __half2float(h2));
        __half l3 = __float2half(v.w - __half2float(h3));
        ((__half2*)lo)[2 * j]     = __half2(l0, l1);
        ((__half2*)lo)[2 * j + 1] = __half2(l2, l3);
    }
}

// ---------------------------------------------------------------------------
// HMMA GEMM fp16x2: C[M,N] = (Ah+Al)[M,K] * B[N,K]^T, B single fp16.
// 3-stage cp.async pipeline, XOR-swizzled smem.
// SPLIT=0: fp32 out. SPLIT=1: single fp16 out.
// ---------------------------------------------------------------------------
#define BM 128
#define BN 128
#define BK 32
#define GT_B  (BM * BK * 2)        // 8192 bytes / tile
#define GSTG_B (3 * GT_B)          // 24576 bytes / stage (Ah, Al, B)
#define GEMM_SMEM (3 * GSTG_B)     // 73728

__device__ __forceinline__ uint32_t gswz(int row, int c) {  // byte offset
    return (uint32_t)(row * BK + ((c ^ ((row >> 1) & 3)) << 3)) * 2;
}

template<int SPLIT>
__global__ __launch_bounds__(256, 2) void gemm_hmma(
    const __half* __restrict__ Ah, const __half* __restrict__ Al,
    const __half* __restrict__ B,
    float* __restrict__ C, __half* __restrict__ Ch,
    int M, int N, int K)
{
    extern __shared__ __half dsm[];
    const uint32_t sb = smem_u32(dsm);
    const int tid = threadIdx.x;
    const int wid = tid >> 5;
    const int lid = tid & 31;
    const int warp_m = (wid & 3) * 32;
    const int warp_n = (wid >> 2) * 64;
    const int brow = blockIdx.y * BM;
    const int bcol = blockIdx.x * BN;

    float acc[2][8][4];
#pragma unroll
    for (int mf = 0; mf < 2; mf++)
#pragma unroll
        for (int nf = 0; nf < 8; nf++)
#pragma unroll
            for (int c = 0; c < 4; c++) acc[mf][nf][c] = 0.f;

    const int r0 = tid >> 2, c0 = tid & 3;
    const uint32_t o0 = gswz(r0, c0);
    const uint32_t o1 = gswz(r0 + 64, c0);
    const int nk = K / BK;

    auto issue = [&](int kt, int st) {
        size_t gA = (size_t)(brow + r0) * K + kt * BK + c0 * 8;
        size_t gB = (size_t)(bcol + r0) * K + kt * BK + c0 * 8;
        size_t gs = (size_t)64 * K;
        uint32_t d = sb + st * GSTG_B;
        cp16(d + o0,            Ah + gA);
        cp16(d + o1,            Ah + gA + gs);
        cp16(d + GT_B + o0,     Al + gA);
        cp16(d + GT_B + o1,     Al + gA + gs);
        cp16(d + 2 * GT_B + o0, B + gB);
        cp16(d + 2 * GT_B + o1, B + gB + gs);
    };

    issue(0, 0); CP_COMMIT();
    issue(1, 1); CP_COMMIT();

    const int a_r = lid & 15;
    const int a_c = lid >> 4;
    const int b_r = (lid & 7) + ((lid >> 4) & 1) * 8;
    const int b_c = (lid >> 3) & 1;

    for (int kt = 0; kt < nk; kt++) {
        int st = kt - (kt / 3) * 3;
        CP_WAIT(1);
        __syncthreads();
        if (kt + 2 < nk) { int k2 = kt + 2; issue(k2, k2 - (k2 / 3) * 3); }
        CP_COMMIT();

        uint32_t uAh = sb + st * GSTG_B;
        uint32_t uAl = uAh + GT_B;
        uint32_t uB  = uAh + 2 * GT_B;

#pragma unroll
        for (int ks = 0; ks < 2; ks++) {
            uint32_t ah[2][4], al[2][4];
#pragma unroll
            for (int mf = 0; mf < 2; mf++) {
                uint32_t off = gswz(warp_m + mf * 16 + a_r, ks * 2 + a_c);
                ldsm_x4(ah[mf], uAh + off);
                ldsm_x4(al[mf], uAl + off);
            }
#pragma unroll
            for (int np = 0; np < 4; np++) {
                uint32_t bb[4];
                uint32_t off = gswz(warp_n + np * 16 + b_r, ks * 2 + b_c);
                ldsm_x4(bb, uB + off);
#pragma unroll
                for (int f = 0; f < 2; f++) {
                    int nf = 2 * np + f;
#pragma unroll
                    for (int mf = 0; mf < 2; mf++) {
                        mma16816(acc[mf][nf], ah[mf], bb + 2 * f);
                        mma16816(acc[mf][nf], al[mf], bb + 2 * f);
                    }
                }
            }
        }
    }

    const int er = lid >> 2;
    const int ec = (lid & 3) * 2;
#pragma unroll
    for (int mf = 0; mf < 2; mf++) {
#pragma unroll
        for (int nf = 0; nf < 8; nf++) {
            int row = brow + warp_m + mf * 16 + er;
            int col = bcol + warp_n + nf * 8 + ec;
            if (SPLIT) {
#pragma unroll
                for (int half = 0; half < 2; half++) {
                    float v0 = acc[mf][nf][2 * half];
                    float v1 = acc[mf][nf][2 * half + 1];
                    size_t o = (size_t)(row + 8 * half) * N + col;
                    *(__half2*)(Ch + o) = __floats2half2_rn(v0, v1);
                }
            } else {
                *(float2*)&C[(size_t)row * N + col] = make_float2(acc[mf][nf][0], acc[mf][nf][1]);
                *(float2*)&C[(size_t)(row + 8) * N + col] = make_float2(acc[mf][nf][2], acc[mf][nf][3]);
            }
        }
    }
}

// ---------------------------------------------------------------------------
// Flash attention (causal) on HMMA fp16: Q,K,V single fp16; P split hi/lo.
// Br = Bc = 64, 128 threads (4 warps), 3-stage cp.async pipeline, XOR swizzle.
// Scale folded into Q (exact 2^-3).
// ---------------------------------------------------------------------------
#define FT_B   (64 * 64 * 2)        // 8192 bytes / tile
#define FSTG_B (2 * FT_B)           // 16384 bytes / stage (K, V)
#define FA_SMEM (3 * FSTG_B)        // 49152

__device__ __forceinline__ uint32_t fswz(int row, int c) {  // byte offset
    return (uint32_t)(row * 64 + ((c ^ (row & 7)) << 3)) * 2;
}

__global__ __launch_bounds__(128, 2) void flash_hmma(
    const __half* __restrict__ qkv,
    __half* __restrict__ ath, __half* __restrict__ atl)
{
    extern __shared__ __half fsm[];
    const uint32_t sb = smem_u32(fsm);
    const int tid = threadIdx.x;
    const int wid = tid >> 5;
    const int lane = tid & 31;
    const int qt = (int)gridDim.x - 1 - (int)blockIdx.x;   // heavy first
    const int bh = blockIdx.y;
    const int b = bh >> 4;
    const int h = bh & 15;
    const int rowbase = b * SEQ;
    const int q0 = qt * 64;
    const int warp_m = wid * 16;

    // ---- stage Q (single fp16), read to regs, fold scale ----
#pragma unroll
    for (int i = 0; i < 4; i++) {
        int v = tid + i * 128;
        int r = v >> 3, c = v & 7;
        size_t g = (size_t)(rowbase + q0 + r) * QKV_N + h * HDIM + c * 8;
        cp16(sb + fswz(r, c), qkv + g);
    }
    CP_COMMIT(); CP_WAIT(0);
    __syncthreads();

    const __half2 sc2 = __half2(__float2half(0.125f), __float2half(0.125f));
    uint32_t Q[4][4];
#pragma unroll
    for (int ks = 0; ks < 4; ks++) {
        uint32_t off = fswz(warp_m + (lane & 15), ks * 2 + (lane >> 4));
        ldsm_x4(Q[ks], sb + off);
#pragma unroll
        for (int i = 0; i < 4; i++) Q[ks][i] = scale_h2(Q[ks][i], sc2);
    }
    __syncthreads();

    float oacc[8][4];
#pragma unroll
    for (int nd = 0; nd < 8; nd++)
#pragma unroll
        for (int c = 0; c < 4; c++) oacc[nd][c] = 0.f;
    float m0 = -1e30f, m1 = -1e30f, l0 = 0.f, l1 = 0.f;

    auto issue_kv = [&](int jt, int st) {
#pragma unroll
        for (int i = 0; i < 4; i++) {
            int v = tid + i * 128;
            int r = v >> 3, c = v & 7;
            size_t g = (size_t)(rowbase + jt * 64 + r) * QKV_N + h * HDIM + c * 8;
            uint32_t d = sb + st * FSTG_B + fswz(r, c);
            cp16(d,        qkv + g + DMODEL);       // K
            cp16(d + FT_B, qkv + g + 2 * DMODEL);   // V
        }
    };

    issue_kv(0, 0); CP_COMMIT();
    if (qt >= 1) issue_kv(1, 1);
    CP_COMMIT();

    const int qrow0 = warp_m + (lane >> 2);
    const int qrow1 = qrow0 + 8;
    const int k_r = (lane & 7) + ((lane >> 4) & 1) * 8;
    const int k_c = (lane >> 3) & 1;
    const int v_r = (lane & 7) + ((lane >> 3) & 1) * 8;
    const int v_c = (lane >> 4) & 1;

    for (int jt = 0; jt <= qt; jt++) {
        int st = jt - (jt / 3) * 3;
        CP_WAIT(1);
        __syncthreads();
        if (jt + 2 <= qt) { int j2 = jt + 2; issue_kv(j2, j2 - (j2 / 3) * 3); }
        CP_COMMIT();

        uint32_t uK = sb + st * FSTG_B;
        uint32_t uV = uK + FT_B;

        // ---- S = (Q*scale) K^T  (single pass) ----
        float sacc[8][4];
#pragma unroll
        for (int nf = 0; nf < 8; nf++)
#pragma unroll
            for (int c = 0; c < 4; c++) sacc[nf][c] = 0.f;

#pragma unroll
        for (int ks = 0; ks < 4; ks++) {
#pragma unroll
            for (int np = 0; np < 4; np++) {
                uint32_t kk[4];
                uint32_t off = fswz(np * 16 + k_r, ks * 2 + k_c);
                ldsm_x4(kk, uK + off);
#pragma unroll
                for (int f = 0; f < 2; f++)
                    mma16816(sacc[2 * np + f], Q[ks], kk + 2 * f);
            }
        }

        // ---- causal mask ----
        if (jt == qt) {
#pragma unroll
            for (int nf = 0; nf < 8; nf++) {
                int col = nf * 8 + (lane & 3) * 2;
                sacc[nf][0] = (col     <= qrow0) ? sacc[nf][0] : -1e30f;
                sacc[nf][1] = (col + 1 <= qrow0) ? sacc[nf][1] : -1e30f;
                sacc[nf][2] = (col     <= qrow1) ? sacc[nf][2] : -1e30f;
                sacc[nf][3] = (col + 1 <= qrow1) ? sacc[nf][3] : -1e30f;
            }
        }

        // ---- online softmax ----
        float mx0 = -1e30f, mx1 = -1e30f;
#pragma unroll
        for (int nf = 0; nf < 8; nf++) {
            mx0 = fmaxf(mx0, fmaxf(sacc[nf][0], sacc[nf][1]));
            mx1 = fmaxf(mx1, fmaxf(sacc[nf][2], sacc[nf][3]));
        }
        mx0 = fmaxf(mx0, __shfl_xor_sync(0xffffffffu, mx0, 1));
        mx0 = fmaxf(mx0, __shfl_xor_sync(0xffffffffu, mx0, 2));
        mx1 = fmaxf(mx1, __shfl_xor_sync(0xffffffffu, mx1, 1));
        mx1 = fmaxf(mx1, __shfl_xor_sync(0xffffffffu, mx1, 2));
        float mn0 = fmaxf(m0, mx0), mn1 = fmaxf(m1, mx1);
        float al0 = __expf(m0 - mn0), al1 = __expf(m1 - mn1);
        float s0 = 0.f, s1 = 0.f;
#pragma unroll
        for (int nf = 0; nf < 8; nf++) {
            sacc[nf][0] = __expf(sacc[nf][0] - mn0); s0 += sacc[nf][0];
            sacc[nf][1] = __expf(sacc[nf][1] - mn0); s0 += sacc[nf][1];
            sacc[nf][2] = __expf(sacc[nf][2] - mn1); s1 += sacc[nf][2];
            sacc[nf][3] = __expf(sacc[nf][3] - mn1); s1 += sacc[nf][3];
        }
        s0 += __shfl_xor_sync(0xffffffffu, s0, 1);
        s0 += __shfl_xor_sync(0xffffffffu, s0, 2);
        s1 += __shfl_xor_sync(0xffffffffu, s1, 1);
        s1 += __shfl_xor_sync(0xffffffffu, s1, 2);
        l0 = l0 * al0 + s0; m0 = mn0;
        l1 = l1 * al1 + s1; m1 = mn1;
#pragma unroll
        for (int nd = 0; nd < 8; nd++) {
            oacc[nd][0] *= al0; oacc[nd][1] *= al0;
            oacc[nd][2] *= al1; oacc[nd][3] *= al1;
        }

        // ---- O += P V  (P split fp16 hi/lo, V single) ----
#pragma unroll
        for (int kb = 0; kb < 4; kb++) {
            uint32_t pah[4], pal[4];
            {
                float v00 = sacc[2 * kb][0],     v01 = sacc[2 * kb][1];
                float v02 = sacc[2 * kb][2],     v03 = sacc[2 * kb][3];
                float v10 = sacc[2 * kb + 1][0], v11 = sacc[2 * kb + 1][1];
                float v12 = sacc[2 * kb + 1][2], v13 = sacc[2 * kb + 1][3];
                pah[0] = pack_h2(v00, v01); pah[1] = pack_h2(v02, v03);
                pah[2] = pack_h2(v10, v11); pah[3] = pack_h2(v12, v13);
                pal[0] = pack_h2(v00 - __half2float(__float2half(v00)),
                                 v01 - __half2float(__float2half(v01)));
                pal[1] = pack_h2(v02 - __half2float(__float2half(v02)),
                                 v03 - __half2float(__float2half(v03)));
                pal[2] = pack_h2(v10 - __half2float(__float2half(v10)),
                                 v11 - __half2float(__float2half(v11)));
                pal[3] = pack_h2(v12 - __half2float(__float2half(v12)),
                                 v13 - __half2float(__float2half(v13)));
            }
#pragma unroll
            for (int ndp = 0; ndp < 4; ndp++) {
                uint32_t vv[4];
                uint32_t off = fswz(kb * 16 + v_r, ndp * 2 + v_c);
                ldsm_x4_t(vv, uV + off);
#pragma unroll
                for (int f = 0; f < 2; f++) {
                    int nd = 2 * ndp + f;
                    mma16816(oacc[nd], pah, vv + 2 * f);
                    mma16816(oacc[nd], pal, vv + 2 * f);
                }
            }
        }
    }

    // ---- epilogue: normalize, split fp16 hi/lo for out-proj ----
    float inv0 = 1.f / l0, inv1 = 1.f / l1;
    int grow0 = rowbase + q0 + qrow0;
#pragma unroll
    for (int nd = 0; nd < 8; nd++) {
        int col = h * HDIM + nd * 8 + (lane & 3) * 2;
#pragma unroll
        for (int half = 0; half < 2; half++) {
            float v0 = oacc[nd][2 * half]     * (half ? inv1 : inv0);
            float v1 = oacc[nd][2 * half + 1] * (half ? inv1 : inv0);
            __half h0 = __float2half(v0), h1 = __float2half(v1);
            __half l0b = __float2half(v0 - __half2float(h0));
            __half l1b = __float2half(v1 - __half2float(h1));
            size_t o = (size_t)(grow0 + 8 * half) * DMODEL + col;
            *(__half2*)(ath + o) = __half2(h0, h1);
            *(__half2*)(atl + o) = __half2(l0b, l1b);
        }
    }
}

// ---------------------------------------------------------------------------
// Launch
// ---------------------------------------------------------------------------
extern "C" void kernel_launch(void* const* d_in, const int* in_sizes, int n_in,
                              void* d_out, int out_size)
{
    (void)in_sizes; (void)n_in; (void)out_size;
    const float* x     = (const float*)d_in[0];
    const float* W_qkv = (const float*)d_in[1];
    const float* W_out = (const float*)d_in[2];
    float* out = (float*)d_out;

    __half *xh, *xl, *wq, *wo, *qkv, *ath, *atl;
    cudaGetSymbolAddress((void**)&xh, g_xh);
    cudaGetSymbolAddress((void**)&xl, g_xl);
    cudaGetSymbolAddress((void**)&wq, g_wq);
    cudaGetSymbolAddress((void**)&wo, g_wo);
    cudaGetSymbolAddress((void**)&qkv, g_qkv);
    cudaGetSymbolAddress((void**)&ath, g_ath);
    cudaGetSymbolAddress((void**)&atl, g_atl);

    cudaFuncSetAttribute(gemm_hmma<0>, cudaFuncAttributeMaxDynamicSharedMemorySize, GEMM_SMEM);
    cudaFuncSetAttribute(gemm_hmma<1>, cudaFuncAttributeMaxDynamicSharedMemorySize, GEMM_SMEM);
    cudaFuncSetAttribute(flash_hmma, cudaFuncAttributeMaxDynamicSharedMemorySize, FA_SMEM);

    split_all<<<(NX4 + NQ4 + NO4 + 255) / 256, 256>>>(
        x, W_qkv, W_out, xh, xl, wq, wo);

    // 1) QKV projection -> single fp16
    gemm_hmma<1><<<dim3(QKV_N / BN, MROWS / BM), 256, GEMM_SMEM>>>(
        xh, xl, wq, nullptr, qkv, MROWS, QKV_N, DMODEL);

    // 2) causal flash attention -> fp16 hi/lo
    flash_hmma<<<dim3(SEQ / 64, BATCH * NHEADS), 128, FA_SMEM>>>(qkv, ath, atl);

    // 3) output projection -> fp32
    gemm_hmma<0><<<dim3(DMODEL / BN, MROWS / BM), 256, GEMM_SMEM>>>(
        ath, atl, wo, out, nullptr, MROWS, DMODEL, DMODEL);
}

// round 14
// speedup vs baseline: 1.8513x; 1.1626x over previous
#include <cuda_runtime.h>
#include <cuda_fp16.h>
#include <stdint.h>

// ---------------------------------------------------------------------------
#define BATCH   2
#define SEQ     2048
#define DMODEL  1024
#define NHEADS  16
#define HDIM    64
#define MROWS   4096
#define QKV_N   3072

// ---------------------------------------------------------------------------
// Scratch (__device__ globals)
// ---------------------------------------------------------------------------
__device__ __half g_xh[(size_t)MROWS * DMODEL];
__device__ __half g_xl[(size_t)MROWS * DMODEL];
__device__ __half g_wq[(size_t)QKV_N * DMODEL];
__device__ __half g_wo[(size_t)DMODEL * DMODEL];
__device__ __half g_qkv[(size_t)MROWS * QKV_N];       // single fp16
__device__ __half g_att[(size_t)MROWS * DMODEL];      // single fp16

// ---------------------------------------------------------------------------
// PTX helpers (all sm_80+ — safe on compute_103)
// ---------------------------------------------------------------------------
__device__ __forceinline__ uint32_t smem_u32(const void* p) {
    uint32_t a;
    asm("{ .reg .u64 t; cvta.to.shared.u64 t, %1; cvt.u32.u64 %0, t; }" : "=r"(a) : "l"(p));
    return a;
}
__device__ __forceinline__ void ldsm_x4(uint32_t* r, uint32_t addr) {
    asm volatile("ldmatrix.sync.aligned.m8n8.x4.shared.b16 {%0,%1,%2,%3}, [%4];"
                 : "=r"(r[0]), "=r"(r[1]), "=r"(r[2]), "=r"(r[3]) : "r"(addr));
}
__device__ __forceinline__ void ldsm_x4_t(uint32_t* r, uint32_t addr) {
    asm volatile("ldmatrix.sync.aligned.m8n8.x4.trans.shared.b16 {%0,%1,%2,%3}, [%4];"
                 : "=r"(r[0]), "=r"(r[1]), "=r"(r[2]), "=r"(r[3]) : "r"(addr));
}
__device__ __forceinline__ void mma16816(float* d, const uint32_t* a, const uint32_t* b) {
    asm volatile(
        "mma.sync.aligned.m16n8k16.row.col.f32.f16.f16.f32 "
        "{%0,%1,%2,%3}, {%4,%5,%6,%7}, {%8,%9}, {%0,%1,%2,%3};"
        : "+f"(d[0]), "+f"(d[1]), "+f"(d[2]), "+f"(d[3])
        : "r"(a[0]), "r"(a[1]), "r"(a[2]), "r"(a[3]), "r"(b[0]), "r"(b[1]));
}
__device__ __forceinline__ void cp16(uint32_t dst, const void* src) {
    asm volatile("cp.async.cg.shared.global [%0], [%1], 16;" :: "r"(dst), "l"(src));
}
#define CP_COMMIT() asm volatile("cp.async.commit_group;" ::: "memory")
#define CP_WAIT(n)  asm volatile("cp.async.wait_group %0;" :: "n"(n) : "memory")

__device__ __forceinline__ uint32_t pack_h2(float a, float b) {
    __half2 t = __floats2half2_rn(a, b);
    return *(uint32_t*)&t;
}
__device__ __forceinline__ uint32_t scale_h2(uint32_t v, __half2 s) {
    __half2 t = __hmul2(*(__half2*)&v, s);
    return *(uint32_t*)&t;
}

// ---------------------------------------------------------------------------
// merged split: fp32 -> fp16 hi (+ lo for x only), three tensors
// ---------------------------------------------------------------------------
#define NX4 (MROWS * DMODEL / 4)
#define NQ4 (QKV_N * DMODEL / 4)
#define NO4 (DMODEL * DMODEL / 4)

__global__ __launch_bounds__(256) void split_all(
    const float* __restrict__ x, const float* __restrict__ wq, const float* __restrict__ wo,
    __half* __restrict__ xh, __half* __restrict__ xl,
    __half* __restrict__ wqh, __half* __restrict__ woh)
{
    int i = blockIdx.x * 256 + threadIdx.x;
    const float* src; __half *hi, *lo; int j;
    if (i < NX4)            { src = x;  hi = xh;  lo = xl;      j = i; }
    else if (i < NX4 + NQ4) { src = wq; hi = wqh; lo = nullptr; j = i - NX4; }
    else if (i < NX4 + NQ4 + NO4) { src = wo; hi = woh; lo = nullptr; j = i - NX4 - NQ4; }
    else return;

    float4 v = ((const float4*)src)[j];
    __half h0 = __float2half(v.x), h1 = __float2half(v.y);
    __half h2 = __float2half(v.z), h3 = __float2half(v.w);
    ((__half2*)hi)[2 * j]     = __half2(h0, h1);
    ((__half2*)hi)[2 * j + 1] = __half2(h2, h3);
    if (lo) {
        __half l0 = __float2half(v.x - __half2float(h0));
        __half l1 = __float2half(v.y - __half2float(h1));
        __half l2 = __float2half(v.z - __half2float(h2));
        __half l3 = __float2half(v.w - __half2float(h3));
        ((__half2*)lo)[2 * j]     = __half2(l0, l1);
        ((__half2*)lo)[2 * j + 1] = __half2(l2, l3);
    }
}

// ---------------------------------------------------------------------------
// HMMA GEMM fp16: C[M,N] = A[M,K] * B[N,K]^T.
// ASPLIT=1: A = Ah + Al (two MMA passes). ASPLIT=0: A single (one pass).
// SPLIT=1: fp16 out; SPLIT=0: fp32 out.
// 3-stage cp.async pipeline, XOR-swizzled smem.
// ---------------------------------------------------------------------------
#define BM 128
#define BN 128
#define BK 32
#define GT_B  (BM * BK * 2)        // 8192 bytes / tile
#define GSTG_B (3 * GT_B)          // 24576 bytes / stage (Ah, [Al], B slots)
#define GEMM_SMEM (3 * GSTG_B)     // 73728

__device__ __forceinline__ uint32_t gswz(int row, int c) {  // byte offset
    return (uint32_t)(row * BK + ((c ^ ((row >> 1) & 3)) << 3)) * 2;
}

template<int ASPLIT, int SPLIT>
__global__ __launch_bounds__(256, 2) void gemm_hmma(
    const __half* __restrict__ Ah, const __half* __restrict__ Al,
    const __half* __restrict__ B,
    float* __restrict__ C, __half* __restrict__ Ch,
    int M, int N, int K)
{
    extern __shared__ __half dsm[];
    const uint32_t sb = smem_u32(dsm);
    const int tid = threadIdx.x;
    const int wid = tid >> 5;
    const int lid = tid & 31;
    const int warp_m = (wid & 3) * 32;
    const int warp_n = (wid >> 2) * 64;
    const int brow = blockIdx.y * BM;
    const int bcol = blockIdx.x * BN;

    float acc[2][8][4];
#pragma unroll
    for (int mf = 0; mf < 2; mf++)
#pragma unroll
        for (int nf = 0; nf < 8; nf++)
#pragma unroll
            for (int c = 0; c < 4; c++) acc[mf][nf][c] = 0.f;

    const int r0 = tid >> 2, c0 = tid & 3;
    const uint32_t o0 = gswz(r0, c0);
    const uint32_t o1 = gswz(r0 + 64, c0);
    const int nk = K / BK;

    auto issue = [&](int kt, int st) {
        size_t gA = (size_t)(brow + r0) * K + kt * BK + c0 * 8;
        size_t gB = (size_t)(bcol + r0) * K + kt * BK + c0 * 8;
        size_t gs = (size_t)64 * K;
        uint32_t d = sb + st * GSTG_B;
        cp16(d + o0,            Ah + gA);
        cp16(d + o1,            Ah + gA + gs);
        if (ASPLIT) {
            cp16(d + GT_B + o0, Al + gA);
            cp16(d + GT_B + o1, Al + gA + gs);
        }
        cp16(d + 2 * GT_B + o0, B + gB);
        cp16(d + 2 * GT_B + o1, B + gB + gs);
    };

    issue(0, 0); CP_COMMIT();
    issue(1, 1); CP_COMMIT();

    const int a_r = lid & 15;
    const int a_c = lid >> 4;
    const int b_r = (lid & 7) + ((lid >> 4) & 1) * 8;
    const int b_c = (lid >> 3) & 1;

    for (int kt = 0; kt < nk; kt++) {
        int st = kt - (kt / 3) * 3;
        CP_WAIT(1);
        __syncthreads();
        if (kt + 2 < nk) { int k2 = kt + 2; issue(k2, k2 - (k2 / 3) * 3); }
        CP_COMMIT();

        uint32_t uAh = sb + st * GSTG_B;
        uint32_t uAl = uAh + GT_B;
        uint32_t uB  = uAh + 2 * GT_B;

#pragma unroll
        for (int ks = 0; ks < 2; ks++) {
            uint32_t ah[2][4], al[2][4];
#pragma unroll
            for (int mf = 0; mf < 2; mf++) {
                uint32_t off = gswz(warp_m + mf * 16 + a_r, ks * 2 + a_c);
                ldsm_x4(ah[mf], uAh + off);
                if (ASPLIT) ldsm_x4(al[mf], uAl + off);
            }
#pragma unroll
            for (int np = 0; np < 4; np++) {
                uint32_t bb[4];
                uint32_t off = gswz(warp_n + np * 16 + b_r, ks * 2 + b_c);
                ldsm_x4(bb, uB + off);
#pragma unroll
                for (int f = 0; f < 2; f++) {
                    int nf = 2 * np + f;
#pragma unroll
                    for (int mf = 0; mf < 2; mf++) {
                        mma16816(acc[mf][nf], ah[mf], bb + 2 * f);
                        if (ASPLIT) mma16816(acc[mf][nf], al[mf], bb + 2 * f);
                    }
                }
            }
        }
    }

    const int er = lid >> 2;
    const int ec = (lid & 3) * 2;
#pragma unroll
    for (int mf = 0; mf < 2; mf++) {
#pragma unroll
        for (int nf = 0; nf < 8; nf++) {
            int row = brow + warp_m + mf * 16 + er;
            int col = bcol + warp_n + nf * 8 + ec;
            if (SPLIT) {
#pragma unroll
                for (int half = 0; half < 2; half++) {
                    size_t o = (size_t)(row + 8 * half) * N + col;
                    *(__half2*)(Ch + o) = __floats2half2_rn(acc[mf][nf][2 * half],
                                                            acc[mf][nf][2 * half + 1]);
                }
            } else {
                *(float2*)&C[(size_t)row * N + col] = make_float2(acc[mf][nf][0], acc[mf][nf][1]);
                *(float2*)&C[(size_t)(row + 8) * N + col] = make_float2(acc[mf][nf][2], acc[mf][nf][3]);
            }
        }
    }
}

// ---------------------------------------------------------------------------
// Flash attention (causal) on HMMA fp16: Q,K,V,P all single fp16.
// Br = Bc = 64, 128 threads (4 warps), 3-stage cp.async pipeline, XOR swizzle.
// Scale folded into Q (exact 2^-3).
// ---------------------------------------------------------------------------
#define FT_B   (64 * 64 * 2)        // 8192 bytes / tile
#define FSTG_B (2 * FT_B)           // 16384 bytes / stage (K, V)
#define FA_SMEM (3 * FSTG_B)        // 49152

__device__ __forceinline__ uint32_t fswz(int row, int c) {  // byte offset
    return (uint32_t)(row * 64 + ((c ^ (row & 7)) << 3)) * 2;
}

__global__ __launch_bounds__(128, 2) void flash_hmma(
    const __half* __restrict__ qkv,
    __half* __restrict__ att)
{
    extern __shared__ __half fsm[];
    const uint32_t sb = smem_u32(fsm);
    const int tid = threadIdx.x;
    const int wid = tid >> 5;
    const int lane = tid & 31;
    const int qt = (int)gridDim.x - 1 - (int)blockIdx.x;   // heavy first
    const int bh = blockIdx.y;
    const int b = bh >> 4;
    const int h = bh & 15;
    const int rowbase = b * SEQ;
    const int q0 = qt * 64;
    const int warp_m = wid * 16;

    // ---- stage Q (single fp16), read to regs, fold scale ----
#pragma unroll
    for (int i = 0; i < 4; i++) {
        int v = tid + i * 128;
        int r = v >> 3, c = v & 7;
        size_t g = (size_t)(rowbase + q0 + r) * QKV_N + h * HDIM + c * 8;
        cp16(sb + fswz(r, c), qkv + g);
    }
    CP_COMMIT(); CP_WAIT(0);
    __syncthreads();

    const __half2 sc2 = __half2(__float2half(0.125f), __float2half(0.125f));
    uint32_t Q[4][4];
#pragma unroll
    for (int ks = 0; ks < 4; ks++) {
        uint32_t off = fswz(warp_m + (lane & 15), ks * 2 + (lane >> 4));
        ldsm_x4(Q[ks], sb + off);
#pragma unroll
        for (int i = 0; i < 4; i++) Q[ks][i] = scale_h2(Q[ks][i], sc2);
    }
    __syncthreads();

    float oacc[8][4];
#pragma unroll
    for (int nd = 0; nd < 8; nd++)
#pragma unroll
        for (int c = 0; c < 4; c++) oacc[nd][c] = 0.f;
    float m0 = -1e30f, m1 = -1e30f, l0 = 0.f, l1 = 0.f;

    auto issue_kv = [&](int jt, int st) {
#pragma unroll
        for (int i = 0; i < 4; i++) {
            int v = tid + i * 128;
            int r = v >> 3, c = v & 7;
            size_t g = (size_t)(rowbase + jt * 64 + r) * QKV_N + h * HDIM + c * 8;
            uint32_t d = sb + st * FSTG_B + fswz(r, c);
            cp16(d,        qkv + g + DMODEL);       // K
            cp16(d + FT_B, qkv + g + 2 * DMODEL);   // V
        }
    };

    issue_kv(0, 0); CP_COMMIT();
    if (qt >= 1) issue_kv(1, 1);
    CP_COMMIT();

    const int qrow0 = warp_m + (lane >> 2);
    const int qrow1 = qrow0 + 8;
    const int k_r = (lane & 7) + ((lane >> 4) & 1) * 8;
    const int k_c = (lane >> 3) & 1;
    const int v_r = (lane & 7) + ((lane >> 3) & 1) * 8;
    const int v_c = (lane >> 4) & 1;

    for (int jt = 0; jt <= qt; jt++) {
        int st = jt - (jt / 3) * 3;
        CP_WAIT(1);
        __syncthreads();
        if (jt + 2 <= qt) { int j2 = jt + 2; issue_kv(j2, j2 - (j2 / 3) * 3); }
        CP_COMMIT();

        uint32_t uK = sb + st * FSTG_B;
        uint32_t uV = uK + FT_B;

        // ---- S = (Q*scale) K^T ----
        float sacc[8][4];
#pragma unroll
        for (int nf = 0; nf < 8; nf++)
#pragma unroll
            for (int c = 0; c < 4; c++) sacc[nf][c] = 0.f;

#pragma unroll
        for (int ks = 0; ks < 4; ks++) {
#pragma unroll
            for (int np = 0; np < 4; np++) {
                uint32_t kk[4];
                uint32_t off = fswz(np * 16 + k_r, ks * 2 + k_c);
                ldsm_x4(kk, uK + off);
#pragma unroll
                for (int f = 0; f < 2; f++)
                    mma16816(sacc[2 * np + f], Q[ks], kk + 2 * f);
            }
        }

        // ---- causal mask ----
        if (jt == qt) {
#pragma unroll
            for (int nf = 0; nf < 8; nf++) {
                int col = nf * 8 + (lane & 3) * 2;
                sacc[nf][0] = (col     <= qrow0) ? sacc[nf][0] : -1e30f;
                sacc[nf][1] = (col + 1 <= qrow0) ? sacc[nf][1] : -1e30f;
                sacc[nf][2] = (col     <= qrow1) ? sacc[nf][2] : -1e30f;
                sacc[nf][3] = (col + 1 <= qrow1) ? sacc[nf][3] : -1e30f;
            }
        }

        // ---- online softmax ----
        float mx0 = -1e30f, mx1 = -1e30f;
#pragma unroll
        for (int nf = 0; nf < 8; nf++) {
            mx0 = fmaxf(mx0, fmaxf(sacc[nf][0], sacc[nf][1]));
            mx1 = fmaxf(mx1, fmaxf(sacc[nf][2], sacc[nf][3]));
        }
        mx0 = fmaxf(mx0, __shfl_xor_sync(0xffffffffu, mx0, 1));
        mx0 = fmaxf(mx0, __shfl_xor_sync(0xffffffffu, mx0, 2));
        mx1 = fmaxf(mx1, __shfl_xor_sync(0xffffffffu, mx1, 1));
        mx1 = fmaxf(mx1, __shfl_xor_sync(0xffffffffu, mx1, 2));
        float mn0 = fmaxf(m0, mx0), mn1 = fmaxf(m1, mx1);
        float al0 = __expf(m0 - mn0), al1 = __expf(m1 - mn1);
        float s0 = 0.f, s1 = 0.f;
#pragma unroll
        for (int nf = 0; nf < 8; nf++) {
            sacc[nf][0] = __expf(sacc[nf][0] - mn0); s0 += sacc[nf][0];
            sacc[nf][1] = __expf(sacc[nf][1] - mn0); s0 += sacc[nf][1];
            sacc[nf][2] = __expf(sacc[nf][2] - mn1); s1 += sacc[nf][2];
            sacc[nf][3] = __expf(sacc[nf][3] - mn1); s1 += sacc[nf][3];
        }
        s0 += __shfl_xor_sync(0xffffffffu, s0, 1);
        s0 += __shfl_xor_sync(0xffffffffu, s0, 2);
        s1 += __shfl_xor_sync(0xffffffffu, s1, 1);
        s1 += __shfl_xor_sync(0xffffffffu, s1, 2);
        l0 = l0 * al0 + s0; m0 = mn0;
        l1 = l1 * al1 + s1; m1 = mn1;
#pragma unroll
        for (int nd = 0; nd < 8; nd++) {
            oacc[nd][0] *= al0; oacc[nd][1] *= al0;
            oacc[nd][2] *= al1; oacc[nd][3] *= al1;
        }

        // ---- O += P V  (P single fp16) ----
#pragma unroll
        for (int kb = 0; kb < 4; kb++) {
            uint32_t pa[4];
            pa[0] = pack_h2(sacc[2 * kb][0],     sacc[2 * kb][1]);
            pa[1] = pack_h2(sacc[2 * kb][2],     sacc[2 * kb][3]);
            pa[2] = pack_h2(sacc[2 * kb + 1][0], sacc[2 * kb + 1][1]);
            pa[3] = pack_h2(sacc[2 * kb + 1][2], sacc[2 * kb + 1][3]);
#pragma unroll
            for (int ndp = 0; ndp < 4; ndp++) {
                uint32_t vv[4];
                uint32_t off = fswz(kb * 16 + v_r, ndp * 2 + v_c);
                ldsm_x4_t(vv, uV + off);
#pragma unroll
                for (int f = 0; f < 2; f++)
                    mma16816(oacc[2 * ndp + f], pa, vv + 2 * f);
            }
        }
    }

    // ---- epilogue: normalize, write single fp16 ----
    float inv0 = 1.f / l0, inv1 = 1.f / l1;
    int grow0 = rowbase + q0 + qrow0;
#pragma unroll
    for (int nd = 0; nd < 8; nd++) {
        int col = h * HDIM + nd * 8 + (lane & 3) * 2;
#pragma unroll
        for (int half = 0; half < 2; half++) {
            float v0 = oacc[nd][2 * half]     * (half ? inv1 : inv0);
            float v1 = oacc[nd][2 * half + 1] * (half ? inv1 : inv0);
            size_t o = (size_t)(grow0 + 8 * half) * DMODEL + col;
            *(__half2*)(att + o) = __floats2half2_rn(v0, v1);
        }
    }
}

// ---------------------------------------------------------------------------
// Launch
// ---------------------------------------------------------------------------
extern "C" void kernel_launch(void* const* d_in, const int* in_sizes, int n_in,
                              void* d_out, int out_size)
{
    (void)in_sizes; (void)n_in; (void)out_size;
    const float* x     = (const float*)d_in[0];
    const float* W_qkv = (const float*)d_in[1];
    const float* W_out = (const float*)d_in[2];
    float* out = (float*)d_out;

    __half *xh, *xl, *wq, *wo, *qkv, *att;
    cudaGetSymbolAddress((void**)&xh, g_xh);
    cudaGetSymbolAddress((void**)&xl, g_xl);
    cudaGetSymbolAddress((void**)&wq, g_wq);
    cudaGetSymbolAddress((void**)&wo, g_wo);
    cudaGetSymbolAddress((void**)&qkv, g_qkv);
    cudaGetSymbolAddress((void**)&att, g_att);

    cudaFuncSetAttribute((const void*)gemm_hmma<1, 1>, cudaFuncAttributeMaxDynamicSharedMemorySize, GEMM_SMEM);
    cudaFuncSetAttribute((const void*)gemm_hmma<0, 0>, cudaFuncAttributeMaxDynamicSharedMemorySize, GEMM_SMEM);
    cudaFuncSetAttribute((const void*)flash_hmma, cudaFuncAttributeMaxDynamicSharedMemorySize, FA_SMEM);

    split_all<<<(NX4 + NQ4 + NO4 + 255) / 256, 256>>>(
        x, W_qkv, W_out, xh, xl, wq, wo);

    // 1) QKV projection: A split (x hi/lo), B single -> fp16
    gemm_hmma<1, 1><<<dim3(QKV_N / BN, MROWS / BM), 256, GEMM_SMEM>>>(
        xh, xl, wq, nullptr, qkv, MROWS, QKV_N, DMODEL);

    // 2) causal flash attention -> single fp16
    flash_hmma<<<dim3(SEQ / 64, BATCH * NHEADS), 128, FA_SMEM>>>(qkv, att);

    // 3) output projection: A single, B single -> fp32
    gemm_hmma<0, 0><<<dim3(DMODEL / BN, MROWS / BM), 256, GEMM_SMEM>>>(
        att, nullptr, wo, out, nullptr, MROWS, DMODEL, DMODEL);
}

// round 15
// speedup vs baseline: 2.4131x; 1.3035x over previous
#include <cuda_runtime.h>
#include <cuda_fp16.h>
#include <stdint.h>

// ---------------------------------------------------------------------------
#define BATCH   2
#define SEQ     2048
#define DMODEL  1024
#define NHEADS  16
#define HDIM    64
#define MROWS   4096
#define QKV_N   3072

// ---------------------------------------------------------------------------
// Scratch (__device__ globals) — everything single fp16
// ---------------------------------------------------------------------------
__device__ __half g_x [(size_t)MROWS * DMODEL];
__device__ __half g_wq[(size_t)QKV_N * DMODEL];
__device__ __half g_wo[(size_t)DMODEL * DMODEL];
__device__ __half g_qkv[(size_t)MROWS * QKV_N];
__device__ __half g_att[(size_t)MROWS * DMODEL];

// ---------------------------------------------------------------------------
// PTX helpers (all sm_80+ — safe on compute_103)
// ---------------------------------------------------------------------------
__device__ __forceinline__ uint32_t smem_u32(const void* p) {
    uint32_t a;
    asm("{ .reg .u64 t; cvta.to.shared.u64 t, %1; cvt.u32.u64 %0, t; }" : "=r"(a) : "l"(p));
    return a;
}
__device__ __forceinline__ void ldsm_x4(uint32_t* r, uint32_t addr) {
    asm volatile("ldmatrix.sync.aligned.m8n8.x4.shared.b16 {%0,%1,%2,%3}, [%4];"
                 : "=r"(r[0]), "=r"(r[1]), "=r"(r[2]), "=r"(r[3]) : "r"(addr));
}
__device__ __forceinline__ void ldsm_x4_t(uint32_t* r, uint32_t addr) {
    asm volatile("ldmatrix.sync.aligned.m8n8.x4.trans.shared.b16 {%0,%1,%2,%3}, [%4];"
                 : "=r"(r[0]), "=r"(r[1]), "=r"(r[2]), "=r"(r[3]) : "r"(addr));
}
__device__ __forceinline__ void mma16816(float* d, const uint32_t* a, const uint32_t* b) {
    asm volatile(
        "mma.sync.aligned.m16n8k16.row.col.f32.f16.f16.f32 "
        "{%0,%1,%2,%3}, {%4,%5,%6,%7}, {%8,%9}, {%0,%1,%2,%3};"
        : "+f"(d[0]), "+f"(d[1]), "+f"(d[2]), "+f"(d[3])
        : "r"(a[0]), "r"(a[1]), "r"(a[2]), "r"(a[3]), "r"(b[0]), "r"(b[1]));
}
__device__ __forceinline__ void cp16(uint32_t dst, const void* src) {
    asm volatile("cp.async.cg.shared.global [%0], [%1], 16;" :: "r"(dst), "l"(src));
}
#define CP_COMMIT() asm volatile("cp.async.commit_group;" ::: "memory")
#define CP_WAIT(n)  asm volatile("cp.async.wait_group %0;" :: "n"(n) : "memory")

__device__ __forceinline__ uint32_t pack_h2(float a, float b) {
    __half2 t = __floats2half2_rn(a, b);
    return *(uint32_t*)&t;
}
__device__ __forceinline__ uint32_t scale_h2(uint32_t v, __half2 s) {
    __half2 t = __hmul2(*(__half2*)&v, s);
    return *(uint32_t*)&t;
}

// ---------------------------------------------------------------------------
// merged convert: fp32 -> fp16, three tensors, one launch
// ---------------------------------------------------------------------------
#define NX4 (MROWS * DMODEL / 4)
#define NQ4 (QKV_N * DMODEL / 4)
#define NO4 (DMODEL * DMODEL / 4)

__global__ __launch_bounds__(256) void cvt_all(
    const float* __restrict__ x, const float* __restrict__ wq, const float* __restrict__ wo,
    __half* __restrict__ xo, __half* __restrict__ wqo, __half* __restrict__ woo)
{
    int i = blockIdx.x * 256 + threadIdx.x;
    const float* src; __half* dst; int j;
    if (i < NX4)            { src = x;  dst = xo;  j = i; }
    else if (i < NX4 + NQ4) { src = wq; dst = wqo; j = i - NX4; }
    else if (i < NX4 + NQ4 + NO4) { src = wo; dst = woo; j = i - NX4 - NQ4; }
    else return;

    float4 v = ((const float4*)src)[j];
    ((__half2*)dst)[2 * j]     = __floats2half2_rn(v.x, v.y);
    ((__half2*)dst)[2 * j + 1] = __floats2half2_rn(v.z, v.w);
}

// ---------------------------------------------------------------------------
// HMMA GEMM fp16: C[M,N] = A[M,K] * B[N,K]^T, all single fp16.
// SPLIT=1: fp16 out; SPLIT=0: fp32 out.
// 3-stage cp.async pipeline, XOR-swizzled smem.
// ---------------------------------------------------------------------------
#define BM 128
#define BN 128
#define BK 32
#define GT_B  (BM * BK * 2)        // 8192 bytes / tile
#define GSTG_B (2 * GT_B)          // 16384 bytes / stage (A, B)
#define GEMM_SMEM (3 * GSTG_B)     // 49152

__device__ __forceinline__ uint32_t gswz(int row, int c) {  // byte offset
    return (uint32_t)(row * BK + ((c ^ ((row >> 1) & 3)) << 3)) * 2;
}

template<int SPLIT>
__global__ __launch_bounds__(256, 2) void gemm_hmma(
    const __half* __restrict__ A, const __half* __restrict__ B,
    float* __restrict__ C, __half* __restrict__ Ch,
    int M, int N, int K)
{
    extern __shared__ __half dsm[];
    const uint32_t sb = smem_u32(dsm);
    const int tid = threadIdx.x;
    const int wid = tid >> 5;
    const int lid = tid & 31;
    const int warp_m = (wid & 3) * 32;
    const int warp_n = (wid >> 2) * 64;
    const int brow = blockIdx.y * BM;
    const int bcol = blockIdx.x * BN;

    float acc[2][8][4];
#pragma unroll
    for (int mf = 0; mf < 2; mf++)
#pragma unroll
        for (int nf = 0; nf < 8; nf++)
#pragma unroll
            for (int c = 0; c < 4; c++) acc[mf][nf][c] = 0.f;

    const int r0 = tid >> 2, c0 = tid & 3;
    const uint32_t o0 = gswz(r0, c0);
    const uint32_t o1 = gswz(r0 + 64, c0);
    const int nk = K / BK;

    auto issue = [&](int kt, int st) {
        size_t gA = (size_t)(brow + r0) * K + kt * BK + c0 * 8;
        size_t gB = (size_t)(bcol + r0) * K + kt * BK + c0 * 8;
        size_t gs = (size_t)64 * K;
        uint32_t d = sb + st * GSTG_B;
        cp16(d + o0,        A + gA);
        cp16(d + o1,        A + gA + gs);
        cp16(d + GT_B + o0, B + gB);
        cp16(d + GT_B + o1, B + gB + gs);
    };

    issue(0, 0); CP_COMMIT();
    issue(1, 1); CP_COMMIT();

    const int a_r = lid & 15;
    const int a_c = lid >> 4;
    const int b_r = (lid & 7) + ((lid >> 4) & 1) * 8;
    const int b_c = (lid >> 3) & 1;

    for (int kt = 0; kt < nk; kt++) {
        int st = kt - (kt / 3) * 3;
        CP_WAIT(1);
        __syncthreads();
        if (kt + 2 < nk) { int k2 = kt + 2; issue(k2, k2 - (k2 / 3) * 3); }
        CP_COMMIT();

        uint32_t uA = sb + st * GSTG_B;
        uint32_t uB = uA + GT_B;

#pragma unroll
        for (int ks = 0; ks < 2; ks++) {
            uint32_t aa[2][4];
#pragma unroll
            for (int mf = 0; mf < 2; mf++) {
                uint32_t off = gswz(warp_m + mf * 16 + a_r, ks * 2 + a_c);
                ldsm_x4(aa[mf], uA + off);
            }
#pragma unroll
            for (int np = 0; np < 4; np++) {
                uint32_t bb[4];
                uint32_t off = gswz(warp_n + np * 16 + b_r, ks * 2 + b_c);
                ldsm_x4(bb, uB + off);
#pragma unroll
                for (int f = 0; f < 2; f++) {
                    int nf = 2 * np + f;
#pragma unroll
                    for (int mf = 0; mf < 2; mf++)
                        mma16816(acc[mf][nf], aa[mf], bb + 2 * f);
                }
            }
        }
    }

    const int er = lid >> 2;
    const int ec = (lid & 3) * 2;
#pragma unroll
    for (int mf = 0; mf < 2; mf++) {
#pragma unroll
        for (int nf = 0; nf < 8; nf++) {
            int row = brow + warp_m + mf * 16 + er;
            int col = bcol + warp_n + nf * 8 + ec;
            if (SPLIT) {
#pragma unroll
                for (int half = 0; half < 2; half++) {
                    size_t o = (size_t)(row + 8 * half) * N + col;
                    *(__half2*)(Ch + o) = __floats2half2_rn(acc[mf][nf][2 * half],
                                                            acc[mf][nf][2 * half + 1]);
                }
            } else {
                *(float2*)&C[(size_t)row * N + col] = make_float2(acc[mf][nf][0], acc[mf][nf][1]);
                *(float2*)&C[(size_t)(row + 8) * N + col] = make_float2(acc[mf][nf][2], acc[mf][nf][3]);
            }
        }
    }
}

// ---------------------------------------------------------------------------
// Flash attention (causal) on HMMA fp16: Q,K,V,P all single fp16.
// Br = Bc = 64, 128 threads (4 warps), 3-stage cp.async pipeline, XOR swizzle.
// Scale folded into Q (exact 2^-3).
// ---------------------------------------------------------------------------
#define FT_B   (64 * 64 * 2)        // 8192 bytes / tile
#define FSTG_B (2 * FT_B)           // 16384 bytes / stage (K, V)
#define FA_SMEM (3 * FSTG_B)        // 49152

__device__ __forceinline__ uint32_t fswz(int row, int c) {  // byte offset
    return (uint32_t)(row * 64 + ((c ^ (row & 7)) << 3)) * 2;
}

__global__ __launch_bounds__(128, 2) void flash_hmma(
    const __half* __restrict__ qkv,
    __half* __restrict__ att)
{
    extern __shared__ __half fsm[];
    const uint32_t sb = smem_u32(fsm);
    const int tid = threadIdx.x;
    const int wid = tid >> 5;
    const int lane = tid & 31;
    const int qt = (int)gridDim.x - 1 - (int)blockIdx.x;   // heavy first
    const int bh = blockIdx.y;
    const int b = bh >> 4;
    const int h = bh & 15;
    const int rowbase = b * SEQ;
    const int q0 = qt * 64;
    const int warp_m = wid * 16;

    // ---- stage Q, read to regs, fold scale ----
#pragma unroll
    for (int i = 0; i < 4; i++) {
        int v = tid + i * 128;
        int r = v >> 3, c = v & 7;
        size_t g = (size_t)(rowbase + q0 + r) * QKV_N + h * HDIM + c * 8;
        cp16(sb + fswz(r, c), qkv + g);
    }
    CP_COMMIT(); CP_WAIT(0);
    __syncthreads();

    const __half2 sc2 = __half2(__float2half(0.125f), __float2half(0.125f));
    uint32_t Q[4][4];
#pragma unroll
    for (int ks = 0; ks < 4; ks++) {
        uint32_t off = fswz(warp_m + (lane & 15), ks * 2 + (lane >> 4));
        ldsm_x4(Q[ks], sb + off);
#pragma unroll
        for (int i = 0; i < 4; i++) Q[ks][i] = scale_h2(Q[ks][i], sc2);
    }
    __syncthreads();

    float oacc[8][4];
#pragma unroll
    for (int nd = 0; nd < 8; nd++)
#pragma unroll
        for (int c = 0; c < 4; c++) oacc[nd][c] = 0.f;
    float m0 = -1e30f, m1 = -1e30f, l0 = 0.f, l1 = 0.f;

    auto issue_kv = [&](int jt, int st) {
#pragma unroll
        for (int i = 0; i < 4; i++) {
            int v = tid + i * 128;
            int r = v >> 3, c = v & 7;
            size_t g = (size_t)(rowbase + jt * 64 + r) * QKV_N + h * HDIM + c * 8;
            uint32_t d = sb + st * FSTG_B + fswz(r, c);
            cp16(d,        qkv + g + DMODEL);       // K
            cp16(d + FT_B, qkv + g + 2 * DMODEL);   // V
        }
    };

    issue_kv(0, 0); CP_COMMIT();
    if (qt >= 1) issue_kv(1, 1);
    CP_COMMIT();

    const int qrow0 = warp_m + (lane >> 2);
    const int qrow1 = qrow0 + 8;
    const int k_r = (lane & 7) + ((lane >> 4) & 1) * 8;
    const int k_c = (lane >> 3) & 1;
    const int v_r = (lane & 7) + ((lane >> 3) & 1) * 8;
    const int v_c = (lane >> 4) & 1;

    for (int jt = 0; jt <= qt; jt++) {
        int st = jt - (jt / 3) * 3;
        CP_WAIT(1);
        __syncthreads();
        if (jt + 2 <= qt) { int j2 = jt + 2; issue_kv(j2, j2 - (j2 / 3) * 3); }
        CP_COMMIT();

        uint32_t uK = sb + st * FSTG_B;
        uint32_t uV = uK + FT_B;

        // ---- S = (Q*scale) K^T ----
        float sacc[8][4];
#pragma unroll
        for (int nf = 0; nf < 8; nf++)
#pragma unroll
            for (int c = 0; c < 4; c++) sacc[nf][c] = 0.f;

#pragma unroll
        for (int ks = 0; ks < 4; ks++) {
#pragma unroll
            for (int np = 0; np < 4; np++) {
                uint32_t kk[4];
                uint32_t off = fswz(np * 16 + k_r, ks * 2 + k_c);
                ldsm_x4(kk, uK + off);
#pragma unroll
                for (int f = 0; f < 2; f++)
                    mma16816(sacc[2 * np + f], Q[ks], kk + 2 * f);
            }
        }

        // ---- causal mask ----
        if (jt == qt) {
#pragma unroll
            for (int nf = 0; nf < 8; nf++) {
                int col = nf * 8 + (lane & 3) * 2;
                sacc[nf][0] = (col     <= qrow0) ? sacc[nf][0] : -1e30f;
                sacc[nf][1] = (col + 1 <= qrow0) ? sacc[nf][1] : -1e30f;
                sacc[nf][2] = (col     <= qrow1) ? sacc[nf][2] : -1e30f;
                sacc[nf][3] = (col + 1 <= qrow1) ? sacc[nf][3] : -1e30f;
            }
        }

        // ---- online softmax ----
        float mx0 = -1e30f, mx1 = -1e30f;
#pragma unroll
        for (int nf = 0; nf < 8; nf++) {
            mx0 = fmaxf(mx0, fmaxf(sacc[nf][0], sacc[nf][1]));
            mx1 = fmaxf(mx1, fmaxf(sacc[nf][2], sacc[nf][3]));
        }
        mx0 = fmaxf(mx0, __shfl_xor_sync(0xffffffffu, mx0, 1));
        mx0 = fmaxf(mx0, __shfl_xor_sync(0xffffffffu, mx0, 2));
        mx1 = fmaxf(mx1, __shfl_xor_sync(0xffffffffu, mx1, 1));
        mx1 = fmaxf(mx1, __shfl_xor_sync(0xffffffffu, mx1, 2));
        float mn0 = fmaxf(m0, mx0), mn1 = fmaxf(m1, mx1);
        float al0 = __expf(m0 - mn0), al1 = __expf(m1 - mn1);
        float s0 = 0.f, s1 = 0.f;
#pragma unroll
        for (int nf = 0; nf < 8; nf++) {
            sacc[nf][0] = __expf(sacc[nf][0] - mn0); s0 += sacc[nf][0];
            sacc[nf][1] = __expf(sacc[nf][1] - mn0); s0 += sacc[nf][1];
            sacc[nf][2] = __expf(sacc[nf][2] - mn1); s1 += sacc[nf][2];
            sacc[nf][3] = __expf(sacc[nf][3] - mn1); s1 += sacc[nf][3];
        }
        s0 += __shfl_xor_sync(0xffffffffu, s0, 1);
        s0 += __shfl_xor_sync(0xffffffffu, s0, 2);
        s1 += __shfl_xor_sync(0xffffffffu, s1, 1);
        s1 += __shfl_xor_sync(0xffffffffu, s1, 2);
        l0 = l0 * al0 + s0; m0 = mn0;
        l1 = l1 * al1 + s1; m1 = mn1;
#pragma unroll
        for (int nd = 0; nd < 8; nd++) {
            oacc[nd][0] *= al0; oacc[nd][1] *= al0;
            oacc[nd][2] *= al1; oacc[nd][3] *= al1;
        }

        // ---- O += P V ----
#pragma unroll
        for (int kb = 0; kb < 4; kb++) {
            uint32_t pa[4];
            pa[0] = pack_h2(sacc[2 * kb][0],     sacc[2 * kb][1]);
            pa[1] = pack_h2(sacc[2 * kb][2],     sacc[2 * kb][3]);
            pa[2] = pack_h2(sacc[2 * kb + 1][0], sacc[2 * kb + 1][1]);
            pa[3] = pack_h2(sacc[2 * kb + 1][2], sacc[2 * kb + 1][3]);
#pragma unroll
            for (int ndp = 0; ndp < 4; ndp++) {
                uint32_t vv[4];
                uint32_t off = fswz(kb * 16 + v_r, ndp * 2 + v_c);
                ldsm_x4_t(vv, uV + off);
#pragma unroll
                for (int f = 0; f < 2; f++)
                    mma16816(oacc[2 * ndp + f], pa, vv + 2 * f);
            }
        }
    }

    // ---- epilogue: normalize, write fp16 ----
    float inv0 = 1.f / l0, inv1 = 1.f / l1;
    int grow0 = rowbase + q0 + qrow0;
#pragma unroll
    for (int nd = 0; nd < 8; nd++) {
        int col = h * HDIM + nd * 8 + (lane & 3) * 2;
#pragma unroll
        for (int half = 0; half < 2; half++) {
            float v0 = oacc[nd][2 * half]     * (half ? inv1 : inv0);
            float v1 = oacc[nd][2 * half + 1] * (half ? inv1 : inv0);
            size_t o = (size_t)(grow0 + 8 * half) * DMODEL + col;
            *(__half2*)(att + o) = __floats2half2_rn(v0, v1);
        }
    }
}

// ---------------------------------------------------------------------------
// Launch
// ---------------------------------------------------------------------------
extern "C" void kernel_launch(void* const* d_in, const int* in_sizes, int n_in,
                              void* d_out, int out_size)
{
    (void)in_sizes; (void)n_in; (void)out_size;
    const float* x     = (const float*)d_in[0];
    const float* W_qkv = (const float*)d_in[1];
    const float* W_out = (const float*)d_in[2];
    float* out = (float*)d_out;

    __half *xf, *wq, *wo, *qkv, *att;
    cudaGetSymbolAddress((void**)&xf, g_x);
    cudaGetSymbolAddress((void**)&wq, g_wq);
    cudaGetSymbolAddress((void**)&wo, g_wo);
    cudaGetSymbolAddress((void**)&qkv, g_qkv);
    cudaGetSymbolAddress((void**)&att, g_att);

    cudaFuncSetAttribute((const void*)gemm_hmma<1>, cudaFuncAttributeMaxDynamicSharedMemorySize, GEMM_SMEM);
    cudaFuncSetAttribute((const void*)gemm_hmma<0>, cudaFuncAttributeMaxDynamicSharedMemorySize, GEMM_SMEM);
    cudaFuncSetAttribute((const void*)flash_hmma, cudaFuncAttributeMaxDynamicSharedMemorySize, FA_SMEM);

    cvt_all<<<(NX4 + NQ4 + NO4 + 255) / 256, 256>>>(x, W_qkv, W_out, xf, wq, wo);

    // 1) QKV projection (pure fp16) -> fp16
    gemm_hmma<1><<<dim3(QKV_N / BN, MROWS / BM), 256, GEMM_SMEM>>>(
        xf, wq, nullptr, qkv, MROWS, QKV_N, DMODEL);

    // 2) causal flash attention -> fp16
    flash_hmma<<<dim3(SEQ / 64, BATCH * NHEADS), 128, FA_SMEM>>>(qkv, att);

    // 3) output projection -> fp32
    gemm_hmma<0><<<dim3(DMODEL / BN, MROWS / BM), 256, GEMM_SMEM>>>(
        att, wo, out, nullptr, MROWS, DMODEL, DMODEL);
}

// round 16
// speedup vs baseline: 2.4871x; 1.0307x over previous
#include <cuda_runtime.h>
#include <cuda_fp16.h>
#include <stdint.h>

// ---------------------------------------------------------------------------
#define BATCH   2
#define SEQ     2048
#define DMODEL  1024
#define NHEADS  16
#define HDIM    64
#define MROWS   4096
#define QKV_N   3072

// ---------------------------------------------------------------------------
// Scratch (__device__ globals) — everything single fp16
// ---------------------------------------------------------------------------
__device__ __half g_x [(size_t)MROWS * DMODEL];
__device__ __half g_wq[(size_t)QKV_N * DMODEL];
__device__ __half g_wo[(size_t)DMODEL * DMODEL];
__device__ __half g_qkv[(size_t)MROWS * QKV_N];
__device__ __half g_att[(size_t)MROWS * DMODEL];

// ---------------------------------------------------------------------------
// PTX helpers (all sm_80+ — safe on compute_103)
// ---------------------------------------------------------------------------
__device__ __forceinline__ uint32_t smem_u32(const void* p) {
    uint32_t a;
    asm("{ .reg .u64 t; cvta.to.shared.u64 t, %1; cvt.u32.u64 %0, t; }" : "=r"(a) : "l"(p));
    return a;
}
__device__ __forceinline__ void ldsm_x4(uint32_t* r, uint32_t addr) {
    asm volatile("ldmatrix.sync.aligned.m8n8.x4.shared.b16 {%0,%1,%2,%3}, [%4];"
                 : "=r"(r[0]), "=r"(r[1]), "=r"(r[2]), "=r"(r[3]) : "r"(addr));
}
__device__ __forceinline__ void ldsm_x4_t(uint32_t* r, uint32_t addr) {
    asm volatile("ldmatrix.sync.aligned.m8n8.x4.trans.shared.b16 {%0,%1,%2,%3}, [%4];"
                 : "=r"(r[0]), "=r"(r[1]), "=r"(r[2]), "=r"(r[3]) : "r"(addr));
}
__device__ __forceinline__ void mma16816(float* d, const uint32_t* a, const uint32_t* b) {
    asm volatile(
        "mma.sync.aligned.m16n8k16.row.col.f32.f16.f16.f32 "
        "{%0,%1,%2,%3}, {%4,%5,%6,%7}, {%8,%9}, {%0,%1,%2,%3};"
        : "+f"(d[0]), "+f"(d[1]), "+f"(d[2]), "+f"(d[3])
        : "r"(a[0]), "r"(a[1]), "r"(a[2]), "r"(a[3]), "r"(b[0]), "r"(b[1]));
}
__device__ __forceinline__ void cp16(uint32_t dst, const void* src) {
    asm volatile("cp.async.cg.shared.global [%0], [%1], 16;" :: "r"(dst), "l"(src));
}
#define CP_COMMIT() asm volatile("cp.async.commit_group;" ::: "memory")
#define CP_WAIT(n)  asm volatile("cp.async.wait_group %0;" :: "n"(n) : "memory")

__device__ __forceinline__ uint32_t pack_h2(float a, float b) {
    __half2 t = __floats2half2_rn(a, b);
    return *(uint32_t*)&t;
}
__device__ __forceinline__ uint32_t scale_h2(uint32_t v, __half2 s) {
    __half2 t = __hmul2(*(__half2*)&v, s);
    return *(uint32_t*)&t;
}

// ---------------------------------------------------------------------------
// merged convert: fp32 -> fp16, three tensors, one launch
// ---------------------------------------------------------------------------
#define NX4 (MROWS * DMODEL / 4)
#define NQ4 (QKV_N * DMODEL / 4)
#define NO4 (DMODEL * DMODEL / 4)

__global__ __launch_bounds__(256) void cvt_all(
    const float* __restrict__ x, const float* __restrict__ wq, const float* __restrict__ wo,
    __half* __restrict__ xo, __half* __restrict__ wqo, __half* __restrict__ woo)
{
    int i = blockIdx.x * 256 + threadIdx.x;
    const float* src; __half* dst; int j;
    if (i < NX4)            { src = x;  dst = xo;  j = i; }
    else if (i < NX4 + NQ4) { src = wq; dst = wqo; j = i - NX4; }
    else if (i < NX4 + NQ4 + NO4) { src = wo; dst = woo; j = i - NX4 - NQ4; }
    else return;

    float4 v = ((const float4*)src)[j];
    ((__half2*)dst)[2 * j]     = __floats2half2_rn(v.x, v.y);
    ((__half2*)dst)[2 * j + 1] = __floats2half2_rn(v.z, v.w);
}

// ---------------------------------------------------------------------------
// HMMA GEMM fp16: C[M,N] = A[M,K] * B[N,K]^T, 64x64 warp tiles.
// 128 threads (4 warps, 2x2), 128x128 CTA tile, BK=32, 3-stage cp.async.
// SPLIT=1: fp16 out; SPLIT=0: fp32 out.
// ---------------------------------------------------------------------------
#define BM 128
#define BN 128
#define BK 32
#define GT_B  (BM * BK * 2)        // 8192 bytes / tile
#define GSTG_B (2 * GT_B)          // 16384 bytes / stage (A, B)
#define GEMM_SMEM (3 * GSTG_B)     // 49152

__device__ __forceinline__ uint32_t gswz(int row, int c) {  // byte offset
    return (uint32_t)(row * BK + ((c ^ ((row >> 1) & 3)) << 3)) * 2;
}

template<int SPLIT>
__global__ __launch_bounds__(128, 2) void gemm_hmma(
    const __half* __restrict__ A, const __half* __restrict__ B,
    float* __restrict__ C, __half* __restrict__ Ch,
    int M, int N, int K)
{
    extern __shared__ __half dsm[];
    const uint32_t sb = smem_u32(dsm);
    const int tid = threadIdx.x;
    const int wid = tid >> 5;
    const int lid = tid & 31;
    const int warp_m = (wid & 1) * 64;
    const int warp_n = (wid >> 1) * 64;
    const int brow = blockIdx.y * BM;
    const int bcol = blockIdx.x * BN;

    float acc[4][8][4];
#pragma unroll
    for (int mf = 0; mf < 4; mf++)
#pragma unroll
        for (int nf = 0; nf < 8; nf++)
#pragma unroll
            for (int c = 0; c < 4; c++) acc[mf][nf][c] = 0.f;

    const int r0 = tid >> 2, c0 = tid & 3;        // 0..31, 0..3
    uint32_t ow[4];
#pragma unroll
    for (int u = 0; u < 4; u++) ow[u] = gswz(r0 + 32 * u, c0);
    const int nk = K / BK;

    auto issue = [&](int kt, int st) {
        uint32_t d = sb + st * GSTG_B;
#pragma unroll
        for (int u = 0; u < 4; u++) {
            size_t gA = (size_t)(brow + r0 + 32 * u) * K + kt * BK + c0 * 8;
            size_t gB = (size_t)(bcol + r0 + 32 * u) * K + kt * BK + c0 * 8;
            cp16(d + ow[u],        A + gA);
            cp16(d + GT_B + ow[u], B + gB);
        }
    };

    issue(0, 0); CP_COMMIT();
    issue(1, 1); CP_COMMIT();

    const int a_r = lid & 15;
    const int a_c = lid >> 4;
    const int b_r = (lid & 7) + ((lid >> 4) & 1) * 8;
    const int b_c = (lid >> 3) & 1;

    for (int kt = 0; kt < nk; kt++) {
        int st = kt - (kt / 3) * 3;
        CP_WAIT(1);
        __syncthreads();
        if (kt + 2 < nk) { int k2 = kt + 2; issue(k2, k2 - (k2 / 3) * 3); }
        CP_COMMIT();

        uint32_t uA = sb + st * GSTG_B;
        uint32_t uB = uA + GT_B;

#pragma unroll
        for (int ks = 0; ks < 2; ks++) {
            uint32_t aa[4][4];
#pragma unroll
            for (int mf = 0; mf < 4; mf++) {
                uint32_t off = gswz(warp_m + mf * 16 + a_r, ks * 2 + a_c);
                ldsm_x4(aa[mf], uA + off);
            }
#pragma unroll
            for (int np = 0; np < 4; np++) {
                uint32_t bb[4];
                uint32_t off = gswz(warp_n + np * 16 + b_r, ks * 2 + b_c);
                ldsm_x4(bb, uB + off);
#pragma unroll
                for (int f = 0; f < 2; f++) {
                    int nf = 2 * np + f;
#pragma unroll
                    for (int mf = 0; mf < 4; mf++)
                        mma16816(acc[mf][nf], aa[mf], bb + 2 * f);
                }
            }
        }
    }

    const int er = lid >> 2;
    const int ec = (lid & 3) * 2;
#pragma unroll
    for (int mf = 0; mf < 4; mf++) {
#pragma unroll
        for (int nf = 0; nf < 8; nf++) {
            int row = brow + warp_m + mf * 16 + er;
            int col = bcol + warp_n + nf * 8 + ec;
            if (SPLIT) {
#pragma unroll
                for (int half = 0; half < 2; half++) {
                    size_t o = (size_t)(row + 8 * half) * N + col;
                    *(__half2*)(Ch + o) = __floats2half2_rn(acc[mf][nf][2 * half],
                                                            acc[mf][nf][2 * half + 1]);
                }
            } else {
                *(float2*)&C[(size_t)row * N + col] = make_float2(acc[mf][nf][0], acc[mf][nf][1]);
                *(float2*)&C[(size_t)(row + 8) * N + col] = make_float2(acc[mf][nf][2], acc[mf][nf][3]);
            }
        }
    }
}

// ---------------------------------------------------------------------------
// Flash attention (causal) on HMMA fp16: Q,K,V,P all single fp16.
// Br = Bc = 64, 128 threads (4 warps), 3-stage cp.async pipeline, XOR swizzle.
// Scale folded into Q (exact 2^-3). (Unchanged from Round 15.)
// ---------------------------------------------------------------------------
#define FT_B   (64 * 64 * 2)        // 8192 bytes / tile
#define FSTG_B (2 * FT_B)           // 16384 bytes / stage (K, V)
#define FA_SMEM (3 * FSTG_B)        // 49152

__device__ __forceinline__ uint32_t fswz(int row, int c) {  // byte offset
    return (uint32_t)(row * 64 + ((c ^ (row & 7)) << 3)) * 2;
}

__global__ __launch_bounds__(128, 2) void flash_hmma(
    const __half* __restrict__ qkv,
    __half* __restrict__ att)
{
    extern __shared__ __half fsm[];
    const uint32_t sb = smem_u32(fsm);
    const int tid = threadIdx.x;
    const int wid = tid >> 5;
    const int lane = tid & 31;
    const int qt = (int)gridDim.x - 1 - (int)blockIdx.x;   // heavy first
    const int bh = blockIdx.y;
    const int b = bh >> 4;
    const int h = bh & 15;
    const int rowbase = b * SEQ;
    const int q0 = qt * 64;
    const int warp_m = wid * 16;

    // ---- stage Q, read to regs, fold scale ----
#pragma unroll
    for (int i = 0; i < 4; i++) {
        int v = tid + i * 128;
        int r = v >> 3, c = v & 7;
        size_t g = (size_t)(rowbase + q0 + r) * QKV_N + h * HDIM + c * 8;
        cp16(sb + fswz(r, c), qkv + g);
    }
    CP_COMMIT(); CP_WAIT(0);
    __syncthreads();

    const __half2 sc2 = __half2(__float2half(0.125f), __float2half(0.125f));
    uint32_t Q[4][4];
#pragma unroll
    for (int ks = 0; ks < 4; ks++) {
        uint32_t off = fswz(warp_m + (lane & 15), ks * 2 + (lane >> 4));
        ldsm_x4(Q[ks], sb + off);
#pragma unroll
        for (int i = 0; i < 4; i++) Q[ks][i] = scale_h2(Q[ks][i], sc2);
    }
    __syncthreads();

    float oacc[8][4];
#pragma unroll
    for (int nd = 0; nd < 8; nd++)
#pragma unroll
        for (int c = 0; c < 4; c++) oacc[nd][c] = 0.f;
    float m0 = -1e30f, m1 = -1e30f, l0 = 0.f, l1 = 0.f;

    auto issue_kv = [&](int jt, int st) {
#pragma unroll
        for (int i = 0; i < 4; i++) {
            int v = tid + i * 128;
            int r = v >> 3, c = v & 7;
            size_t g = (size_t)(rowbase + jt * 64 + r) * QKV_N + h * HDIM + c * 8;
            uint32_t d = sb + st * FSTG_B + fswz(r, c);
            cp16(d,        qkv + g + DMODEL);       // K
            cp16(d + FT_B, qkv + g + 2 * DMODEL);   // V
        }
    };

    issue_kv(0, 0); CP_COMMIT();
    if (qt >= 1) issue_kv(1, 1);
    CP_COMMIT();

    const int qrow0 = warp_m + (lane >> 2);
    const int qrow1 = qrow0 + 8;
    const int k_r = (lane & 7) + ((lane >> 4) & 1) * 8;
    const int k_c = (lane >> 3) & 1;
    const int v_r = (lane & 7) + ((lane >> 3) & 1) * 8;
    const int v_c = (lane >> 4) & 1;

    for (int jt = 0; jt <= qt; jt++) {
        int st = jt - (jt / 3) * 3;
        CP_WAIT(1);
        __syncthreads();
        if (jt + 2 <= qt) { int j2 = jt + 2; issue_kv(j2, j2 - (j2 / 3) * 3); }
        CP_COMMIT();

        uint32_t uK = sb + st * FSTG_B;
        uint32_t uV = uK + FT_B;

        // ---- S = (Q*scale) K^T ----
        float sacc[8][4];
#pragma unroll
        for (int nf = 0; nf < 8; nf++)
#pragma unroll
            for (int c = 0; c < 4; c++) sacc[nf][c] = 0.f;

#pragma unroll
        for (int ks = 0; ks < 4; ks++) {
#pragma unroll
            for (int np = 0; np < 4; np++) {
                uint32_t kk[4];
                uint32_t off = fswz(np * 16 + k_r, ks * 2 + k_c);
                ldsm_x4(kk, uK + off);
#pragma unroll
                for (int f = 0; f < 2; f++)
                    mma16816(sacc[2 * np + f], Q[ks], kk + 2 * f);
            }
        }

        // ---- causal mask ----
        if (jt == qt) {
#pragma unroll
            for (int nf = 0; nf < 8; nf++) {
                int col = nf * 8 + (lane & 3) * 2;
                sacc[nf][0] = (col     <= qrow0) ? sacc[nf][0] : -1e30f;
                sacc[nf][1] = (col + 1 <= qrow0) ? sacc[nf][1] : -1e30f;
                sacc[nf][2] = (col     <= qrow1) ? sacc[nf][2] : -1e30f;
                sacc[nf][3] = (col + 1 <= qrow1) ? sacc[nf][3] : -1e30f;
            }
        }

        // ---- online softmax ----
        float mx0 = -1e30f, mx1 = -1e30f;
#pragma unroll
        for (int nf = 0; nf < 8; nf++) {
            mx0 = fmaxf(mx0, fmaxf(sacc[nf][0], sacc[nf][1]));
            mx1 = fmaxf(mx1, fmaxf(sacc[nf][2], sacc[nf][3]));
        }
        mx0 = fmaxf(mx0, __shfl_xor_sync(0xffffffffu, mx0, 1));
        mx0 = fmaxf(mx0, __shfl_xor_sync(0xffffffffu, mx0, 2));
        mx1 = fmaxf(mx1, __shfl_xor_sync(0xffffffffu, mx1, 1));
        mx1 = fmaxf(mx1, __shfl_xor_sync(0xffffffffu, mx1, 2));
        float mn0 = fmaxf(m0, mx0), mn1 = fmaxf(m1, mx1);
        float al0 = __expf(m0 - mn0), al1 = __expf(m1 - mn1);
        float s0 = 0.f, s1 = 0.f;
#pragma unroll
        for (int nf = 0; nf < 8; nf++) {
            sacc[nf][0] = __expf(sacc[nf][0] - mn0); s0 += sacc[nf][0];
            sacc[nf][1] = __expf(sacc[nf][1] - mn0); s0 += sacc[nf][1];
            sacc[nf][2] = __expf(sacc[nf][2] - mn1); s1 += sacc[nf][2];
            sacc[nf][3] = __expf(sacc[nf][3] - mn1); s1 += sacc[nf][3];
        }
        s0 += __shfl_xor_sync(0xffffffffu, s0, 1);
        s0 += __shfl_xor_sync(0xffffffffu, s0, 2);
        s1 += __shfl_xor_sync(0xffffffffu, s1, 1);
        s1 += __shfl_xor_sync(0xffffffffu, s1, 2);
        l0 = l0 * al0 + s0; m0 = mn0;
        l1 = l1 * al1 + s1; m1 = mn1;
#pragma unroll
        for (int nd = 0; nd < 8; nd++) {
            oacc[nd][0] *= al0; oacc[nd][1] *= al0;
            oacc[nd][2] *= al1; oacc[nd][3] *= al1;
        }

        // ---- O += P V ----
#pragma unroll
        for (int kb = 0; kb < 4; kb++) {
            uint32_t pa[4];
            pa[0] = pack_h2(sacc[2 * kb][0],     sacc[2 * kb][1]);
            pa[1] = pack_h2(sacc[2 * kb][2],     sacc[2 * kb][3]);
            pa[2] = pack_h2(sacc[2 * kb + 1][0], sacc[2 * kb + 1][1]);
            pa[3] = pack_h2(sacc[2 * kb + 1][2], sacc[2 * kb + 1][3]);
#pragma unroll
            for (int ndp = 0; ndp < 4; ndp++) {
                uint32_t vv[4];
                uint32_t off = fswz(kb * 16 + v_r, ndp * 2 + v_c);
                ldsm_x4_t(vv, uV + off);
#pragma unroll
                for (int f = 0; f < 2; f++)
                    mma16816(oacc[2 * ndp + f], pa, vv + 2 * f);
            }
        }
    }

    // ---- epilogue: normalize, write fp16 ----
    float inv0 = 1.f / l0, inv1 = 1.f / l1;
    int grow0 = rowbase + q0 + qrow0;
#pragma unroll
    for (int nd = 0; nd < 8; nd++) {
        int col = h * HDIM + nd * 8 + (lane & 3) * 2;
#pragma unroll
        for (int half = 0; half < 2; half++) {
            float v0 = oacc[nd][2 * half]     * (half ? inv1 : inv0);
            float v1 = oacc[nd][2 * half + 1] * (half ? inv1 : inv0);
            size_t o = (size_t)(grow0 + 8 * half) * DMODEL + col;
            *(__half2*)(att + o) = __floats2half2_rn(v0, v1);
        }
    }
}

// ---------------------------------------------------------------------------
// Launch
// ---------------------------------------------------------------------------
extern "C" void kernel_launch(void* const* d_in, const int* in_sizes, int n_in,
                              void* d_out, int out_size)
{
    (void)in_sizes; (void)n_in; (void)out_size;
    const float* x     = (const float*)d_in[0];
    const float* W_qkv = (const float*)d_in[1];
    const float* W_out = (const float*)d_in[2];
    float* out = (float*)d_out;

    __half *xf, *wq, *wo, *qkv, *att;
    cudaGetSymbolAddress((void**)&xf, g_x);
    cudaGetSymbolAddress((void**)&wq, g_wq);
    cudaGetSymbolAddress((void**)&wo, g_wo);
    cudaGetSymbolAddress((void**)&qkv, g_qkv);
    cudaGetSymbolAddress((void**)&att, g_att);

    cudaFuncSetAttribute((const void*)gemm_hmma<1>, cudaFuncAttributeMaxDynamicSharedMemorySize, GEMM_SMEM);
    cudaFuncSetAttribute((const void*)gemm_hmma<0>, cudaFuncAttributeMaxDynamicSharedMemorySize, GEMM_SMEM);
    cudaFuncSetAttribute((const void*)flash_hmma, cudaFuncAttributeMaxDynamicSharedMemorySize, FA_SMEM);

    cvt_all<<<(NX4 + NQ4 + NO4 + 255) / 256, 256>>>(x, W_qkv, W_out, xf, wq, wo);

    // 1) QKV projection (pure fp16, 64x64 warp tiles) -> fp16
    gemm_hmma<1><<<dim3(QKV_N / BN, MROWS / BM), 128, GEMM_SMEM>>>(
        xf, wq, nullptr, qkv, MROWS, QKV_N, DMODEL);

    // 2) causal flash attention -> fp16
    flash_hmma<<<dim3(SEQ / 64, BATCH * NHEADS), 128, FA_SMEM>>>(qkv, att);

    // 3) output projection -> fp32
    gemm_hmma<0><<<dim3(DMODEL / BN, MROWS / BM), 128, GEMM_SMEM>>>(
        att, wo, out, nullptr, MROWS, DMODEL, DMODEL);
}